// round 6
// baseline (speedup 1.0000x reference)
#include <cuda_runtime.h>
#include <cuda_bf16.h>
#include <math.h>
#include <stdint.h>

#define BATCH 4
#define SEQ   1024
#define QDIM  512
#define NH    8
#define HD    64
#define BH    (BATCH*NH)
#define OUT_ELEMS  (BATCH*SEQ*HD)
#define PROJ_ELEMS (BATCH*NH*SEQ*HD)
#define NROWS (BH*SEQ)
#define QCHUNKS 4

__device__ float g_q[PROJ_ELEMS];
__device__ float g_k[PROJ_ELEMS];
__device__ float g_v[PROJ_ELEMS];
__device__ float g_cpart[QCHUNKS*PROJ_ELEMS];
__device__ float g_partial[NROWS * 8];
__device__ float g_rinv[NROWS];

// ---------------------------------------------------------------------------
// bf16 split helpers
// ---------------------------------------------------------------------------
__device__ __forceinline__ uint32_t packbf(float x, float y){
    __nv_bfloat162 t = __floats2bfloat162_rn(x, y);
    return *(uint32_t*)&t;
}
__device__ __forceinline__ void packsplit(float x, float y, uint32_t& hi, uint32_t& lo){
    __nv_bfloat16 xh = __float2bfloat16_rn(x);
    __nv_bfloat16 yh = __float2bfloat16_rn(y);
    __nv_bfloat162 h; h.x = xh; h.y = yh;
    hi = *(uint32_t*)&h;
    lo = packbf(x - __bfloat162float(xh), y - __bfloat162float(yh));
}
__device__ __forceinline__ void mmabf(float c[4], const uint32_t a[4], const uint32_t b[2]){
    asm volatile("mma.sync.aligned.m16n8k16.row.col.f32.bf16.bf16.f32 "
        "{%0,%1,%2,%3},{%4,%5,%6,%7},{%8,%9},{%0,%1,%2,%3};"
        : "+f"(c[0]),"+f"(c[1]),"+f"(c[2]),"+f"(c[3])
        : "r"(a[0]),"r"(a[1]),"r"(a[2]),"r"(a[3]),"r"(b[0]),"r"(b[1]));
}
__device__ __forceinline__ void ldA(const uint32_t* S, int str, int row0, int kp, uint32_t a[4]){
    int lane = threadIdx.x & 31; int gr = lane>>2, tc = lane&3;
    const uint32_t* p = S + (row0+gr)*str + kp + tc;
    a[0]=p[0]; a[1]=p[8*str]; a[2]=p[4]; a[3]=p[8*str+4];
}
__device__ __forceinline__ void ldB(const uint32_t* S, int str, int n0, int kp, uint32_t b[2]){
    int lane = threadIdx.x & 31;
    const uint32_t* p = S + (n0+(lane>>2))*str + kp + (lane&3);
    b[0]=p[0]; b[1]=p[4];
}

// ---------------------------------------------------------------------------
// Kernel 1: all three projections  Y = X @ W^T + b  (3-term bf16) -> [b,h,l,d]
// ---------------------------------------------------------------------------
__global__ __launch_bounds__(256) void proj_all_kernel(
        const float* __restrict__ x0, const float* __restrict__ x1, const float* __restrict__ x2,
        const float* __restrict__ w0, const float* __restrict__ w1, const float* __restrict__ w2,
        const float* __restrict__ b0, const float* __restrict__ b1, const float* __restrict__ b2){
    __shared__ uint32_t Xhi[128*17], Xlo[128*17];
    __shared__ uint32_t Whi[64*17],  Wlo[64*17];
    int sel = blockIdx.z;
    const float* X = sel==0 ? x0 : sel==1 ? x1 : x2;
    const float* W = sel==0 ? w0 : sel==1 ? w1 : w2;
    const float* bias = sel==0 ? b0 : sel==1 ? b1 : b2;
    float* dst = sel==0 ? g_q : sel==1 ? g_k : g_v;

    int tid = threadIdx.x;
    int h = blockIdx.x, n0 = h*64;
    int m0 = blockIdx.y*128;
    int w = tid>>5, wm = w>>1, wn = w&1;
    int lane = tid&31, gr = lane>>2, c2 = (lane&3)*2;

    float acc[2][4][4] = {};
    for (int k0=0; k0<QDIM; k0+=32){
        __syncthreads();
        #pragma unroll
        for (int i=0;i<4;i++){
            int lin = tid + i*256;
            int r = lin>>3, c4 = lin&7;
            float4 xv = *(const float4*)(X + (size_t)(m0+r)*QDIM + k0 + c4*4);
            uint32_t h0,l0,h1,l1;
            packsplit(xv.x, xv.y, h0, l0);
            packsplit(xv.z, xv.w, h1, l1);
            Xhi[r*17 + c4*2]   = h0; Xhi[r*17 + c4*2+1] = h1;
            Xlo[r*17 + c4*2]   = l0; Xlo[r*17 + c4*2+1] = l1;
        }
        #pragma unroll
        for (int i=0;i<2;i++){
            int lin = tid + i*256;
            int r = lin>>3, c4 = lin&7;
            float4 wv = *(const float4*)(W + (size_t)(n0+r)*QDIM + k0 + c4*4);
            uint32_t h0,l0,h1,l1;
            packsplit(wv.x, wv.y, h0, l0);
            packsplit(wv.z, wv.w, h1, l1);
            Whi[r*17 + c4*2]   = h0; Whi[r*17 + c4*2+1] = h1;
            Wlo[r*17 + c4*2]   = l0; Wlo[r*17 + c4*2+1] = l1;
        }
        __syncthreads();
        #pragma unroll
        for (int ks=0; ks<2; ks++){
            int kp = ks*8;
            uint32_t ah[2][4], al[2][4];
            #pragma unroll
            for (int mi=0;mi<2;mi++){
                ldA(Xhi,17, wm*32+mi*16, kp, ah[mi]);
                ldA(Xlo,17, wm*32+mi*16, kp, al[mi]);
            }
            #pragma unroll
            for (int ni=0;ni<4;ni++){
                uint32_t bh_[2], bl_[2];
                ldB(Whi,17, wn*32+ni*8, kp, bh_);
                ldB(Wlo,17, wn*32+ni*8, kp, bl_);
                #pragma unroll
                for (int mi=0;mi<2;mi++){
                    mmabf(acc[mi][ni], ah[mi], bh_);
                    mmabf(acc[mi][ni], ah[mi], bl_);
                    mmabf(acc[mi][ni], al[mi], bh_);
                }
            }
        }
    }
    int b = m0>>10, l0 = m0&1023;
    float* base = dst + (size_t)(b*NH+h)*SEQ*HD;
    #pragma unroll
    for (int mi=0;mi<2;mi++)
    #pragma unroll
    for (int ni=0;ni<4;ni++){
        int row = l0 + wm*32 + mi*16 + gr;
        int col = wn*32 + ni*8 + c2;
        float2 bb = *(const float2*)(bias + n0 + col);
        float2 v0 = {acc[mi][ni][0]+bb.x, acc[mi][ni][1]+bb.y};
        float2 v1 = {acc[mi][ni][2]+bb.x, acc[mi][ni][3]+bb.y};
        *(float2*)(base + (size_t)row*HD + col) = v0;
        *(float2*)(base + (size_t)(row+8)*HD + col) = v1;
    }
}

// ---------------------------------------------------------------------------
// Kernel 2: P = exp(0.5 * Q K^T) (3-term bf16) -> attn (unnormalized) + partials
// grid (8 kb, 8 qb, 32 bh), 512 threads, tile 128q x 128k, warp 32x32
// Epilogue stages P through (dead) Q/K smem for coalesced 512B-row stores.
// ---------------------------------------------------------------------------
__global__ __launch_bounds__(512) void scores_exp_kernel(float* __restrict__ attn){
    __shared__ uint32_t SB[4*128*17];    // Q/K hi/lo planes; reused as P staging
    __shared__ float sums[128][4];
    uint32_t* Qhi = SB;
    uint32_t* Qlo = SB + 128*17;
    uint32_t* Khi = SB + 2*128*17;
    uint32_t* Klo = SB + 3*128*17;

    int tid = threadIdx.x;
    int kb = blockIdx.x, q0b = blockIdx.y*128, bh = blockIdx.z;
    int w = tid>>5, wq = w>>2, wk = w&3;
    int lane = tid&31, gr = lane>>2, c2 = (lane&3)*2;
    const float* Qg = g_q + (size_t)(bh*SEQ + q0b)*HD;
    const float* Kg = g_k + (size_t)(bh*SEQ + kb*128)*HD;

    float acc[2][4][4] = {};
    #pragma unroll
    for (int dt=0; dt<2; dt++){
        int d0 = dt*32;
        __syncthreads();
        #pragma unroll
        for (int i=0;i<2;i++){
            int lin = tid + i*512;
            int r = lin>>3, c4 = lin&7;
            float4 xq = *(const float4*)(Qg + (size_t)r*HD + d0 + c4*4);
            float4 xk = *(const float4*)(Kg + (size_t)r*HD + d0 + c4*4);
            uint32_t h0,l0,h1,l1;
            packsplit(xq.x, xq.y, h0, l0); packsplit(xq.z, xq.w, h1, l1);
            Qhi[r*17 + c4*2] = h0; Qhi[r*17 + c4*2+1] = h1;
            Qlo[r*17 + c4*2] = l0; Qlo[r*17 + c4*2+1] = l1;
            packsplit(xk.x, xk.y, h0, l0); packsplit(xk.z, xk.w, h1, l1);
            Khi[r*17 + c4*2] = h0; Khi[r*17 + c4*2+1] = h1;
            Klo[r*17 + c4*2] = l0; Klo[r*17 + c4*2+1] = l1;
        }
        __syncthreads();
        #pragma unroll
        for (int ks=0; ks<2; ks++){
            int kp = ks*8;
            uint32_t ah[2][4], al[2][4];
            #pragma unroll
            for (int mi=0;mi<2;mi++){
                ldA(Qhi,17, wq*32+mi*16, kp, ah[mi]);
                ldA(Qlo,17, wq*32+mi*16, kp, al[mi]);
            }
            #pragma unroll
            for (int ni=0;ni<4;ni++){
                uint32_t bh_[2], bl_[2];
                ldB(Khi,17, wk*32+ni*8, kp, bh_);
                ldB(Klo,17, wk*32+ni*8, kp, bl_);
                #pragma unroll
                for (int mi=0;mi<2;mi++){
                    mmabf(acc[mi][ni], ah[mi], bh_);
                    mmabf(acc[mi][ni], ah[mi], bl_);
                    mmabf(acc[mi][ni], al[mi], bh_);
                }
            }
        }
    }

    // exp in place + row-sum partials (register path, before staging)
    float rs[2][2] = {};
    #pragma unroll
    for (int mi=0;mi<2;mi++)
    #pragma unroll
    for (int ni=0;ni<4;ni++){
        acc[mi][ni][0] = __expf(acc[mi][ni][0]*0.5f);
        acc[mi][ni][1] = __expf(acc[mi][ni][1]*0.5f);
        acc[mi][ni][2] = __expf(acc[mi][ni][2]*0.5f);
        acc[mi][ni][3] = __expf(acc[mi][ni][3]*0.5f);
        rs[mi][0] += acc[mi][ni][0] + acc[mi][ni][1];
        rs[mi][1] += acc[mi][ni][2] + acc[mi][ni][3];
    }
    #pragma unroll
    for (int mi=0;mi<2;mi++)
    #pragma unroll
    for (int j=0;j<2;j++){
        float s = rs[mi][j];
        s += __shfl_xor_sync(0xffffffffu, s, 1);
        s += __shfl_xor_sync(0xffffffffu, s, 2);
        rs[mi][j] = s;
    }
    if ((lane&3)==0){
        #pragma unroll
        for (int mi=0;mi<2;mi++)
        #pragma unroll
        for (int j=0;j<2;j++)
            sums[wq*32 + mi*16 + gr + j*8][wk] = rs[mi][j];
    }
    __syncthreads();
    if (tid < 128){
        float t = sums[tid][0] + sums[tid][1] + sums[tid][2] + sums[tid][3];
        g_partial[(((size_t)bh*SEQ + q0b + tid)<<3) + kb] = t;
    }

    // staged coalesced stores: two passes of 64 rows via smem
    float* Ab = attn + (size_t)bh*SEQ*SEQ;
    float* Pst = (float*)SB;             // 64 x 132 floats = 8448 <= 8704 words
    #pragma unroll
    for (int pass=0; pass<2; pass++){
        __syncthreads();
        if ((wq>>1) == pass){
            int rloc = (wq&1)*32;
            #pragma unroll
            for (int mi=0;mi<2;mi++)
            #pragma unroll
            for (int ni=0;ni<4;ni++){
                int row = rloc + mi*16 + gr;
                int col = wk*32 + ni*8 + c2;
                float2 v0 = {acc[mi][ni][0], acc[mi][ni][1]};
                float2 v1 = {acc[mi][ni][2], acc[mi][ni][3]};
                *(float2*)&Pst[row*132 + col]     = v0;
                *(float2*)&Pst[(row+8)*132 + col] = v1;
            }
        }
        __syncthreads();
        int rowbase = q0b + pass*64;
        #pragma unroll
        for (int j=0;j<4;j++){
            int idx = tid + j*512;
            int r = idx>>5, c = (idx&31)*4;
            *(float4*)(Ab + (size_t)(rowbase+r)*SEQ + kb*128 + c) = *(float4*)&Pst[r*132 + c];
        }
    }
}

// ---------------------------------------------------------------------------
// Kernel 3: row-sum reduce -> 1/S
// ---------------------------------------------------------------------------
__global__ __launch_bounds__(256) void rowsum_kernel(){
    int r = blockIdx.x*256 + threadIdx.x;
    const float* p = g_partial + ((size_t)r<<3);
    float s = ((p[0]+p[1])+(p[2]+p[3])) + ((p[4]+p[5])+(p[6]+p[7]));
    g_rinv[r] = 1.0f / s;
}

// ---------------------------------------------------------------------------
// Kernel 4: normalize attn in place + PARTIAL context (3-term bf16)
// grid (16 n-tiles of 64, 32 bh, 4 q-chunks) = 2048 blocks, 256 threads.
// Block tile: M=64(d) x N=64(kpos), q-reduction 256. Warp m16 x n32.
// ---------------------------------------------------------------------------
__global__ __launch_bounds__(256) void context_norm_kernel(float* __restrict__ attn){
    __shared__ uint32_t Vhi[64*17], Vlo[64*17];
    __shared__ uint32_t Ahi[64*17], Alo[64*17];
    int tid = threadIdx.x;
    int nb = blockIdx.x*64, bh = blockIdx.y, qc = blockIdx.z;
    int w = tid>>5, wm = w>>1, wn = w&1;   // wm: 4 x m16 (d), wn: 2 x n32
    int lane = tid&31, gr = lane>>2, tc = lane&3;
    float* Ag = attn + (size_t)bh*SEQ*SEQ + nb;
    const float* Vg = g_v + (size_t)bh*SEQ*HD;
    const float* rinv = g_rinv + (size_t)bh*SEQ;

    float acc[4][4] = {};
    int qlo = qc*(SEQ/QCHUNKS), qhi_ = qlo + SEQ/QCHUNKS;
    for (int q0=qlo; q0<qhi_; q0+=32){
        __syncthreads();
        // V tile 32q x 64d -> packed [d][qp]
        #pragma unroll
        for (int i=0;i<4;i++){
            int p = tid + i*256;
            int d = p & 63, qp = p >> 6;
            float v0 = Vg[(size_t)(q0+2*qp)*HD + d];
            float v1 = Vg[(size_t)(q0+2*qp+1)*HD + d];
            uint32_t hh, ll; packsplit(v0, v1, hh, ll);
            Vhi[d*17+qp] = hh; Vlo[d*17+qp] = ll;
        }
        // A tile 32q x 64k: normalize, write back, pack transposed [kpos][qp]
        {
            int c4 = tid & 15, qp = tid >> 4;
            size_t o0 = (size_t)(q0+2*qp)*SEQ + c4*4;
            size_t o1 = o0 + SEQ;
            float4 a0 = *(const float4*)(Ag + o0);
            float4 a1 = *(const float4*)(Ag + o1);
            float i0 = rinv[q0+2*qp], i1 = rinv[q0+2*qp+1];
            a0.x*=i0; a0.y*=i0; a0.z*=i0; a0.w*=i0;
            a1.x*=i1; a1.y*=i1; a1.z*=i1; a1.w*=i1;
            *(float4*)(Ag + o0) = a0;
            *(float4*)(Ag + o1) = a1;
            uint32_t hh, ll;
            packsplit(a0.x, a1.x, hh, ll); Ahi[(c4*4+0)*17+qp]=hh; Alo[(c4*4+0)*17+qp]=ll;
            packsplit(a0.y, a1.y, hh, ll); Ahi[(c4*4+1)*17+qp]=hh; Alo[(c4*4+1)*17+qp]=ll;
            packsplit(a0.z, a1.z, hh, ll); Ahi[(c4*4+2)*17+qp]=hh; Alo[(c4*4+2)*17+qp]=ll;
            packsplit(a0.w, a1.w, hh, ll); Ahi[(c4*4+3)*17+qp]=hh; Alo[(c4*4+3)*17+qp]=ll;
        }
        __syncthreads();
        #pragma unroll
        for (int ks=0; ks<2; ks++){
            int kp = ks*8;
            uint32_t ah[4], al[4];
            ldA(Vhi,17, wm*16, kp, ah);
            ldA(Vlo,17, wm*16, kp, al);
            #pragma unroll
            for (int ni=0;ni<4;ni++){
                uint32_t bh_[2], bl_[2];
                ldB(Ahi,17, wn*32+ni*8, kp, bh_);
                ldB(Alo,17, wn*32+ni*8, kp, bl_);
                mmabf(acc[ni], ah, bh_);
                mmabf(acc[ni], ah, bl_);
                mmabf(acc[ni], al, bh_);
            }
        }
    }
    float* Cb = g_cpart + (size_t)qc*PROJ_ELEMS + (size_t)bh*SEQ*HD;
    #pragma unroll
    for (int ni=0;ni<4;ni++){
        int drow = wm*16 + gr;
        int col  = nb + wn*32 + ni*8 + tc*2;
        Cb[(size_t)col*HD + drow]         = acc[ni][0];
        Cb[(size_t)(col+1)*HD + drow]     = acc[ni][1];
        Cb[(size_t)col*HD + drow+8]       = acc[ni][2];
        Cb[(size_t)(col+1)*HD + drow+8]   = acc[ni][3];
    }
}

// ---------------------------------------------------------------------------
// Kernel 5: output = (sum of 4 ctx partials) @ wp^T + bp   (3-term bf16)
// ---------------------------------------------------------------------------
__global__ __launch_bounds__(256) void outproj_kernel(const float* __restrict__ W,
        const float* __restrict__ bias, float* __restrict__ out){
    __shared__ uint32_t Chi[128*17], Clo[128*17];
    __shared__ uint32_t Whi[64*17],  Wlo[64*17];
    int tid = threadIdx.x;
    int m0 = blockIdx.x*128;
    int b = m0>>10, l0 = m0&1023;
    int w = tid>>5, wm = w>>1, wn = w&1;
    int lane = tid&31, gr = lane>>2, c2 = (lane&3)*2;

    float acc[2][4][4] = {};
    for (int k0=0; k0<QDIM; k0+=32){
        int h = k0>>6, off = k0&63;
        const float* Cg = g_cpart + ((size_t)(b*NH+h)*SEQ + l0)*HD + off;
        __syncthreads();
        #pragma unroll
        for (int i=0;i<4;i++){
            int lin = tid + i*256;
            int r = lin>>3, c4 = lin&7;
            size_t o = (size_t)r*HD + c4*4;
            float4 a0 = *(const float4*)(Cg + o);
            float4 a1 = *(const float4*)(Cg + (size_t)PROJ_ELEMS + o);
            float4 a2 = *(const float4*)(Cg + (size_t)2*PROJ_ELEMS + o);
            float4 a3 = *(const float4*)(Cg + (size_t)3*PROJ_ELEMS + o);
            float4 s;
            s.x = (a0.x+a1.x)+(a2.x+a3.x);
            s.y = (a0.y+a1.y)+(a2.y+a3.y);
            s.z = (a0.z+a1.z)+(a2.z+a3.z);
            s.w = (a0.w+a1.w)+(a2.w+a3.w);
            uint32_t h0,l0_,h1,l1;
            packsplit(s.x, s.y, h0, l0_);
            packsplit(s.z, s.w, h1, l1);
            Chi[r*17 + c4*2] = h0; Chi[r*17 + c4*2+1] = h1;
            Clo[r*17 + c4*2] = l0_; Clo[r*17 + c4*2+1] = l1;
        }
        #pragma unroll
        for (int i=0;i<2;i++){
            int lin = tid + i*256;
            int r = lin>>3, c4 = lin&7;
            float4 wv = *(const float4*)(W + (size_t)r*QDIM + k0 + c4*4);
            uint32_t h0,l0_,h1,l1;
            packsplit(wv.x, wv.y, h0, l0_);
            packsplit(wv.z, wv.w, h1, l1);
            Whi[r*17 + c4*2] = h0; Whi[r*17 + c4*2+1] = h1;
            Wlo[r*17 + c4*2] = l0_; Wlo[r*17 + c4*2+1] = l1;
        }
        __syncthreads();
        #pragma unroll
        for (int ks=0; ks<2; ks++){
            int kp = ks*8;
            uint32_t ah[2][4], al[2][4];
            #pragma unroll
            for (int mi=0;mi<2;mi++){
                ldA(Chi,17, wm*32+mi*16, kp, ah[mi]);
                ldA(Clo,17, wm*32+mi*16, kp, al[mi]);
            }
            #pragma unroll
            for (int ni=0;ni<4;ni++){
                uint32_t bh_[2], bl_[2];
                ldB(Whi,17, wn*32+ni*8, kp, bh_);
                ldB(Wlo,17, wn*32+ni*8, kp, bl_);
                #pragma unroll
                for (int mi=0;mi<2;mi++){
                    mmabf(acc[mi][ni], ah[mi], bh_);
                    mmabf(acc[mi][ni], ah[mi], bl_);
                    mmabf(acc[mi][ni], al[mi], bh_);
                }
            }
        }
    }
    #pragma unroll
    for (int mi=0;mi<2;mi++)
    #pragma unroll
    for (int ni=0;ni<4;ni++){
        int row = m0 + wm*32 + mi*16 + gr;
        int col = wn*32 + ni*8 + c2;
        float2 bb = *(const float2*)(bias + col);
        float2 v0 = {acc[mi][ni][0]+bb.x, acc[mi][ni][1]+bb.y};
        float2 v1 = {acc[mi][ni][2]+bb.x, acc[mi][ni][3]+bb.y};
        *(float2*)(out + (size_t)row*HD + col) = v0;
        *(float2*)(out + (size_t)(row+8)*HD + col) = v1;
    }
}

// ---------------------------------------------------------------------------
extern "C" void kernel_launch(void* const* d_in, const int* in_sizes, int n_in,
                              void* d_out, int out_size) {
    const float* q  = (const float*)d_in[0];
    const float* k  = (const float*)d_in[1];
    const float* v  = (const float*)d_in[2];
    const float* wq = (const float*)d_in[3];
    const float* bq = (const float*)d_in[4];
    const float* wk = (const float*)d_in[5];
    const float* bk = (const float*)d_in[6];
    const float* wv = (const float*)d_in[7];
    const float* bv = (const float*)d_in[8];
    const float* wp = (const float*)d_in[9];
    const float* bp = (const float*)d_in[10];

    float* out  = (float*)d_out;
    float* attn = out + OUT_ELEMS;

    dim3 projGrid(NH, (BATCH*SEQ)/128, 3);            // (8, 32, 3)
    proj_all_kernel<<<projGrid, 256>>>(q, k, v, wq, wk, wv, bq, bk, bv);

    dim3 scoreGrid(SEQ/128, SEQ/128, BH);             // (8, 8, 32)
    scores_exp_kernel<<<scoreGrid, 512>>>(attn);

    rowsum_kernel<<<NROWS/256, 256>>>();

    dim3 ctxGrid(SEQ/64, BH, QCHUNKS);                // (16, 32, 4)
    context_norm_kernel<<<ctxGrid, 256>>>(attn);

    outproj_kernel<<<(BATCH*SEQ)/128, 256>>>(wp, bp, out);
}

// round 7
// speedup vs baseline: 1.0477x; 1.0477x over previous
#include <cuda_runtime.h>
#include <cuda_bf16.h>
#include <math.h>
#include <stdint.h>

#define BATCH 4
#define SEQ   1024
#define QDIM  512
#define NH    8
#define HD    64
#define BH    (BATCH*NH)
#define OUT_ELEMS  (BATCH*SEQ*HD)
#define PROJ_ELEMS (BATCH*NH*SEQ*HD)
#define NROWS (BH*SEQ)
#define QCHUNKS 4

__device__ float g_q[PROJ_ELEMS];
__device__ float g_k[PROJ_ELEMS];
__device__ float g_v[PROJ_ELEMS];
__device__ float g_cpart[QCHUNKS*PROJ_ELEMS];
__device__ float g_partial[NROWS * 8];
__device__ float g_rinv[NROWS];

// ---------------------------------------------------------------------------
// bf16 split helpers
// ---------------------------------------------------------------------------
__device__ __forceinline__ uint32_t packbf(float x, float y){
    __nv_bfloat162 t = __floats2bfloat162_rn(x, y);
    return *(uint32_t*)&t;
}
__device__ __forceinline__ void packsplit(float x, float y, uint32_t& hi, uint32_t& lo){
    __nv_bfloat16 xh = __float2bfloat16_rn(x);
    __nv_bfloat16 yh = __float2bfloat16_rn(y);
    __nv_bfloat162 h; h.x = xh; h.y = yh;
    hi = *(uint32_t*)&h;
    lo = packbf(x - __bfloat162float(xh), y - __bfloat162float(yh));
}
__device__ __forceinline__ void mmabf(float c[4], const uint32_t a[4], const uint32_t b[2]){
    asm volatile("mma.sync.aligned.m16n8k16.row.col.f32.bf16.bf16.f32 "
        "{%0,%1,%2,%3},{%4,%5,%6,%7},{%8,%9},{%0,%1,%2,%3};"
        : "+f"(c[0]),"+f"(c[1]),"+f"(c[2]),"+f"(c[3])
        : "r"(a[0]),"r"(a[1]),"r"(a[2]),"r"(a[3]),"r"(b[0]),"r"(b[1]));
}
__device__ __forceinline__ void ldA(const uint32_t* S, int str, int row0, int kp, uint32_t a[4]){
    int lane = threadIdx.x & 31; int gr = lane>>2, tc = lane&3;
    const uint32_t* p = S + (row0+gr)*str + kp + tc;
    a[0]=p[0]; a[1]=p[8*str]; a[2]=p[4]; a[3]=p[8*str+4];
}
__device__ __forceinline__ void ldB(const uint32_t* S, int str, int n0, int kp, uint32_t b[2]){
    int lane = threadIdx.x & 31;
    const uint32_t* p = S + (n0+(lane>>2))*str + kp + (lane&3);
    b[0]=p[0]; b[1]=p[4];
}

// ---------------------------------------------------------------------------
// Kernel 1: all three projections  Y = X @ W^T + b  (3-term bf16) -> [b,h,l,d]
// ---------------------------------------------------------------------------
__global__ __launch_bounds__(256) void proj_all_kernel(
        const float* __restrict__ x0, const float* __restrict__ x1, const float* __restrict__ x2,
        const float* __restrict__ w0, const float* __restrict__ w1, const float* __restrict__ w2,
        const float* __restrict__ b0, const float* __restrict__ b1, const float* __restrict__ b2){
    __shared__ uint32_t Xhi[128*17], Xlo[128*17];
    __shared__ uint32_t Whi[64*17],  Wlo[64*17];
    int sel = blockIdx.z;
    const float* X = sel==0 ? x0 : sel==1 ? x1 : x2;
    const float* W = sel==0 ? w0 : sel==1 ? w1 : w2;
    const float* bias = sel==0 ? b0 : sel==1 ? b1 : b2;
    float* dst = sel==0 ? g_q : sel==1 ? g_k : g_v;

    int tid = threadIdx.x;
    int h = blockIdx.x, n0 = h*64;
    int m0 = blockIdx.y*128;
    int w = tid>>5, wm = w>>1, wn = w&1;
    int lane = tid&31, gr = lane>>2, c2 = (lane&3)*2;

    float acc[2][4][4] = {};
    for (int k0=0; k0<QDIM; k0+=32){
        __syncthreads();
        #pragma unroll
        for (int i=0;i<4;i++){
            int lin = tid + i*256;
            int r = lin>>3, c4 = lin&7;
            float4 xv = *(const float4*)(X + (size_t)(m0+r)*QDIM + k0 + c4*4);
            uint32_t h0,l0,h1,l1;
            packsplit(xv.x, xv.y, h0, l0);
            packsplit(xv.z, xv.w, h1, l1);
            Xhi[r*17 + c4*2]   = h0; Xhi[r*17 + c4*2+1] = h1;
            Xlo[r*17 + c4*2]   = l0; Xlo[r*17 + c4*2+1] = l1;
        }
        #pragma unroll
        for (int i=0;i<2;i++){
            int lin = tid + i*256;
            int r = lin>>3, c4 = lin&7;
            float4 wv = *(const float4*)(W + (size_t)(n0+r)*QDIM + k0 + c4*4);
            uint32_t h0,l0,h1,l1;
            packsplit(wv.x, wv.y, h0, l0);
            packsplit(wv.z, wv.w, h1, l1);
            Whi[r*17 + c4*2]   = h0; Whi[r*17 + c4*2+1] = h1;
            Wlo[r*17 + c4*2]   = l0; Wlo[r*17 + c4*2+1] = l1;
        }
        __syncthreads();
        #pragma unroll
        for (int ks=0; ks<2; ks++){
            int kp = ks*8;
            uint32_t ah[2][4], al[2][4];
            #pragma unroll
            for (int mi=0;mi<2;mi++){
                ldA(Xhi,17, wm*32+mi*16, kp, ah[mi]);
                ldA(Xlo,17, wm*32+mi*16, kp, al[mi]);
            }
            #pragma unroll
            for (int ni=0;ni<4;ni++){
                uint32_t bh_[2], bl_[2];
                ldB(Whi,17, wn*32+ni*8, kp, bh_);
                ldB(Wlo,17, wn*32+ni*8, kp, bl_);
                #pragma unroll
                for (int mi=0;mi<2;mi++){
                    mmabf(acc[mi][ni], ah[mi], bh_);
                    mmabf(acc[mi][ni], ah[mi], bl_);
                    mmabf(acc[mi][ni], al[mi], bh_);
                }
            }
        }
    }
    int b = m0>>10, l0 = m0&1023;
    float* base = dst + (size_t)(b*NH+h)*SEQ*HD;
    #pragma unroll
    for (int mi=0;mi<2;mi++)
    #pragma unroll
    for (int ni=0;ni<4;ni++){
        int row = l0 + wm*32 + mi*16 + gr;
        int col = wn*32 + ni*8 + c2;
        float2 bb = *(const float2*)(bias + n0 + col);
        float2 v0 = {acc[mi][ni][0]+bb.x, acc[mi][ni][1]+bb.y};
        float2 v1 = {acc[mi][ni][2]+bb.x, acc[mi][ni][3]+bb.y};
        *(float2*)(base + (size_t)row*HD + col) = v0;
        *(float2*)(base + (size_t)(row+8)*HD + col) = v1;
    }
}

// ---------------------------------------------------------------------------
// Kernel 2: P = exp(0.5 * Q K^T) (3-term bf16) -> attn (unnormalized) + partials
// grid (8 kb, 8 qb, 32 bh), 512 threads, tile 128q x 128k, warp 32x32
// (R5 epilogue: direct float2 stores — staged version regressed)
// ---------------------------------------------------------------------------
__global__ __launch_bounds__(512) void scores_exp_kernel(float* __restrict__ attn){
    __shared__ uint32_t Qhi[128*17], Qlo[128*17];
    __shared__ uint32_t Khi[128*17], Klo[128*17];
    __shared__ float sums[128][4];

    int tid = threadIdx.x;
    int kb = blockIdx.x, q0b = blockIdx.y*128, bh = blockIdx.z;
    int w = tid>>5, wq = w>>2, wk = w&3;
    int lane = tid&31, gr = lane>>2, c2 = (lane&3)*2;
    const float* Qg = g_q + (size_t)(bh*SEQ + q0b)*HD;
    const float* Kg = g_k + (size_t)(bh*SEQ + kb*128)*HD;

    float acc[2][4][4] = {};
    #pragma unroll
    for (int dt=0; dt<2; dt++){
        int d0 = dt*32;
        __syncthreads();
        #pragma unroll
        for (int i=0;i<2;i++){
            int lin = tid + i*512;
            int r = lin>>3, c4 = lin&7;
            float4 xq = *(const float4*)(Qg + (size_t)r*HD + d0 + c4*4);
            float4 xk = *(const float4*)(Kg + (size_t)r*HD + d0 + c4*4);
            uint32_t h0,l0,h1,l1;
            packsplit(xq.x, xq.y, h0, l0); packsplit(xq.z, xq.w, h1, l1);
            Qhi[r*17 + c4*2] = h0; Qhi[r*17 + c4*2+1] = h1;
            Qlo[r*17 + c4*2] = l0; Qlo[r*17 + c4*2+1] = l1;
            packsplit(xk.x, xk.y, h0, l0); packsplit(xk.z, xk.w, h1, l1);
            Khi[r*17 + c4*2] = h0; Khi[r*17 + c4*2+1] = h1;
            Klo[r*17 + c4*2] = l0; Klo[r*17 + c4*2+1] = l1;
        }
        __syncthreads();
        #pragma unroll
        for (int ks=0; ks<2; ks++){
            int kp = ks*8;
            uint32_t ah[2][4], al[2][4];
            #pragma unroll
            for (int mi=0;mi<2;mi++){
                ldA(Qhi,17, wq*32+mi*16, kp, ah[mi]);
                ldA(Qlo,17, wq*32+mi*16, kp, al[mi]);
            }
            #pragma unroll
            for (int ni=0;ni<4;ni++){
                uint32_t bh_[2], bl_[2];
                ldB(Khi,17, wk*32+ni*8, kp, bh_);
                ldB(Klo,17, wk*32+ni*8, kp, bl_);
                #pragma unroll
                for (int mi=0;mi<2;mi++){
                    mmabf(acc[mi][ni], ah[mi], bh_);
                    mmabf(acc[mi][ni], ah[mi], bl_);
                    mmabf(acc[mi][ni], al[mi], bh_);
                }
            }
        }
    }

    float* Ab = attn + (size_t)bh*SEQ*SEQ;
    float rs[2][2] = {};
    #pragma unroll
    for (int mi=0;mi<2;mi++)
    #pragma unroll
    for (int ni=0;ni<4;ni++){
        float e0 = __expf(acc[mi][ni][0]*0.5f);
        float e1 = __expf(acc[mi][ni][1]*0.5f);
        float e2 = __expf(acc[mi][ni][2]*0.5f);
        float e3 = __expf(acc[mi][ni][3]*0.5f);
        int row = q0b + wq*32 + mi*16 + gr;
        int col = kb*128 + wk*32 + ni*8 + c2;
        float2 v0 = {e0, e1}, v1 = {e2, e3};
        *(float2*)(Ab + (size_t)row*SEQ + col) = v0;
        *(float2*)(Ab + (size_t)(row+8)*SEQ + col) = v1;
        rs[mi][0] += e0 + e1;
        rs[mi][1] += e2 + e3;
    }
    #pragma unroll
    for (int mi=0;mi<2;mi++)
    #pragma unroll
    for (int j=0;j<2;j++){
        float s = rs[mi][j];
        s += __shfl_xor_sync(0xffffffffu, s, 1);
        s += __shfl_xor_sync(0xffffffffu, s, 2);
        rs[mi][j] = s;
    }
    if ((lane&3)==0){
        #pragma unroll
        for (int mi=0;mi<2;mi++)
        #pragma unroll
        for (int j=0;j<2;j++)
            sums[wq*32 + mi*16 + gr + j*8][wk] = rs[mi][j];
    }
    __syncthreads();
    if (tid < 128){
        float t = sums[tid][0] + sums[tid][1] + sums[tid][2] + sums[tid][3];
        g_partial[(((size_t)bh*SEQ + q0b + tid)<<3) + kb] = t;
    }
}

// ---------------------------------------------------------------------------
// Kernel 3: row-sum reduce -> 1/S
// ---------------------------------------------------------------------------
__global__ __launch_bounds__(256) void rowsum_kernel(){
    int r = blockIdx.x*256 + threadIdx.x;
    const float* p = g_partial + ((size_t)r<<3);
    float s = ((p[0]+p[1])+(p[2]+p[3])) + ((p[4]+p[5])+(p[6]+p[7]));
    g_rinv[r] = 1.0f / s;
}

// ---------------------------------------------------------------------------
// Kernel 4: normalize attn in place + PARTIAL context (3-term bf16)
// grid (16 n-tiles of 64, 32 bh, 4 q-chunks), 256 threads.
// Software-pipelined: next tile's A/V prefetched to registers during MMA.
// ---------------------------------------------------------------------------
__global__ __launch_bounds__(256) void context_norm_kernel(float* __restrict__ attn){
    __shared__ uint32_t Vhi[64*17], Vlo[64*17];
    __shared__ uint32_t Ahi[64*17], Alo[64*17];
    int tid = threadIdx.x;
    int nb = blockIdx.x*64, bh = blockIdx.y, qc = blockIdx.z;
    int w = tid>>5, wm = w>>1, wn = w&1;   // wm: 4 x m16 (d), wn: 2 x n32
    int lane = tid&31, gr = lane>>2, tc = lane&3;
    float* Ag = attn + (size_t)bh*SEQ*SEQ + nb;
    const float* Vg = g_v + (size_t)bh*SEQ*HD;
    const float* rinv = g_rinv + (size_t)bh*SEQ;

    // per-thread fixed source indices
    int ac4 = tid & 15, aqp = tid >> 4;          // A tile: 2 rows x 4 cols
    float vr[4][2];                               // V prefetch regs
    float4 ar0, ar1; float ri0, ri1;              // A prefetch regs

    #define CTX_LOADV(Q0)                                             \
        _Pragma("unroll")                                             \
        for (int i=0;i<4;i++){                                        \
            int p = tid + i*256; int d = p & 63, qp = p >> 6;         \
            vr[i][0] = Vg[(size_t)((Q0)+2*qp)*HD + d];                \
            vr[i][1] = Vg[(size_t)((Q0)+2*qp+1)*HD + d];              \
        }
    #define CTX_LOADA(Q0) {                                           \
        size_t o0 = (size_t)((Q0)+2*aqp)*SEQ + ac4*4;                 \
        ar0 = *(const float4*)(Ag + o0);                              \
        ar1 = *(const float4*)(Ag + o0 + SEQ);                        \
        ri0 = rinv[(Q0)+2*aqp]; ri1 = rinv[(Q0)+2*aqp+1];             \
    }

    float acc[4][4] = {};
    int qlo = qc*(SEQ/QCHUNKS), qhi_ = qlo + SEQ/QCHUNKS;
    CTX_LOADV(qlo);
    CTX_LOADA(qlo);
    for (int q0=qlo; q0<qhi_; q0+=32){
        // pack phase: current regs -> smem (+ normalized attn write-back)
        #pragma unroll
        for (int i=0;i<4;i++){
            int p = tid + i*256; int d = p & 63, qp = p >> 6;
            uint32_t hh, ll; packsplit(vr[i][0], vr[i][1], hh, ll);
            Vhi[d*17+qp] = hh; Vlo[d*17+qp] = ll;
        }
        {
            float4 a0 = ar0, a1 = ar1;
            a0.x*=ri0; a0.y*=ri0; a0.z*=ri0; a0.w*=ri0;
            a1.x*=ri1; a1.y*=ri1; a1.z*=ri1; a1.w*=ri1;
            size_t o0 = (size_t)(q0+2*aqp)*SEQ + ac4*4;
            *(float4*)(Ag + o0) = a0;
            *(float4*)(Ag + o0 + SEQ) = a1;
            uint32_t hh, ll;
            packsplit(a0.x, a1.x, hh, ll); Ahi[(ac4*4+0)*17+aqp]=hh; Alo[(ac4*4+0)*17+aqp]=ll;
            packsplit(a0.y, a1.y, hh, ll); Ahi[(ac4*4+1)*17+aqp]=hh; Alo[(ac4*4+1)*17+aqp]=ll;
            packsplit(a0.z, a1.z, hh, ll); Ahi[(ac4*4+2)*17+aqp]=hh; Alo[(ac4*4+2)*17+aqp]=ll;
            packsplit(a0.w, a1.w, hh, ll); Ahi[(ac4*4+3)*17+aqp]=hh; Alo[(ac4*4+3)*17+aqp]=ll;
        }
        __syncthreads();
        // prefetch next tile while MMAs run
        if (q0+32 < qhi_){
            CTX_LOADV(q0+32);
            CTX_LOADA(q0+32);
        }
        #pragma unroll
        for (int ks=0; ks<2; ks++){
            int kp = ks*8;
            uint32_t ah[4], al[4];
            ldA(Vhi,17, wm*16, kp, ah);
            ldA(Vlo,17, wm*16, kp, al);
            #pragma unroll
            for (int ni=0;ni<4;ni++){
                uint32_t bh_[2], bl_[2];
                ldB(Ahi,17, wn*32+ni*8, kp, bh_);
                ldB(Alo,17, wn*32+ni*8, kp, bl_);
                mmabf(acc[ni], ah, bh_);
                mmabf(acc[ni], ah, bl_);
                mmabf(acc[ni], al, bh_);
            }
        }
        __syncthreads();
    }
    #undef CTX_LOADV
    #undef CTX_LOADA

    float* Cb = g_cpart + (size_t)qc*PROJ_ELEMS + (size_t)bh*SEQ*HD;
    #pragma unroll
    for (int ni=0;ni<4;ni++){
        int drow = wm*16 + gr;
        int col  = nb + wn*32 + ni*8 + tc*2;
        Cb[(size_t)col*HD + drow]         = acc[ni][0];
        Cb[(size_t)(col+1)*HD + drow]     = acc[ni][1];
        Cb[(size_t)col*HD + drow+8]       = acc[ni][2];
        Cb[(size_t)(col+1)*HD + drow+8]   = acc[ni][3];
    }
}

// ---------------------------------------------------------------------------
// Kernel 5: output = (sum of 4 ctx partials) @ wp^T + bp   (3-term bf16)
// ---------------------------------------------------------------------------
__global__ __launch_bounds__(256) void outproj_kernel(const float* __restrict__ W,
        const float* __restrict__ bias, float* __restrict__ out){
    __shared__ uint32_t Chi[128*17], Clo[128*17];
    __shared__ uint32_t Whi[64*17],  Wlo[64*17];
    int tid = threadIdx.x;
    int m0 = blockIdx.x*128;
    int b = m0>>10, l0 = m0&1023;
    int w = tid>>5, wm = w>>1, wn = w&1;
    int lane = tid&31, gr = lane>>2, c2 = (lane&3)*2;

    float acc[2][4][4] = {};
    for (int k0=0; k0<QDIM; k0+=32){
        int h = k0>>6, off = k0&63;
        const float* Cg = g_cpart + ((size_t)(b*NH+h)*SEQ + l0)*HD + off;
        __syncthreads();
        #pragma unroll
        for (int i=0;i<4;i++){
            int lin = tid + i*256;
            int r = lin>>3, c4 = lin&7;
            size_t o = (size_t)r*HD + c4*4;
            float4 a0 = *(const float4*)(Cg + o);
            float4 a1 = *(const float4*)(Cg + (size_t)PROJ_ELEMS + o);
            float4 a2 = *(const float4*)(Cg + (size_t)2*PROJ_ELEMS + o);
            float4 a3 = *(const float4*)(Cg + (size_t)3*PROJ_ELEMS + o);
            float4 s;
            s.x = (a0.x+a1.x)+(a2.x+a3.x);
            s.y = (a0.y+a1.y)+(a2.y+a3.y);
            s.z = (a0.z+a1.z)+(a2.z+a3.z);
            s.w = (a0.w+a1.w)+(a2.w+a3.w);
            uint32_t h0,l0_,h1,l1;
            packsplit(s.x, s.y, h0, l0_);
            packsplit(s.z, s.w, h1, l1);
            Chi[r*17 + c4*2] = h0; Chi[r*17 + c4*2+1] = h1;
            Clo[r*17 + c4*2] = l0_; Clo[r*17 + c4*2+1] = l1;
        }
        #pragma unroll
        for (int i=0;i<2;i++){
            int lin = tid + i*256;
            int r = lin>>3, c4 = lin&7;
            float4 wv = *(const float4*)(W + (size_t)r*QDIM + k0 + c4*4);
            uint32_t h0,l0_,h1,l1;
            packsplit(wv.x, wv.y, h0, l0_);
            packsplit(wv.z, wv.w, h1, l1);
            Whi[r*17 + c4*2] = h0; Whi[r*17 + c4*2+1] = h1;
            Wlo[r*17 + c4*2] = l0_; Wlo[r*17 + c4*2+1] = l1;
        }
        __syncthreads();
        #pragma unroll
        for (int ks=0; ks<2; ks++){
            int kp = ks*8;
            uint32_t ah[2][4], al[2][4];
            #pragma unroll
            for (int mi=0;mi<2;mi++){
                ldA(Chi,17, wm*32+mi*16, kp, ah[mi]);
                ldA(Clo,17, wm*32+mi*16, kp, al[mi]);
            }
            #pragma unroll
            for (int ni=0;ni<4;ni++){
                uint32_t bh_[2], bl_[2];
                ldB(Whi,17, wn*32+ni*8, kp, bh_);
                ldB(Wlo,17, wn*32+ni*8, kp, bl_);
                #pragma unroll
                for (int mi=0;mi<2;mi++){
                    mmabf(acc[mi][ni], ah[mi], bh_);
                    mmabf(acc[mi][ni], ah[mi], bl_);
                    mmabf(acc[mi][ni], al[mi], bh_);
                }
            }
        }
    }
    #pragma unroll
    for (int mi=0;mi<2;mi++)
    #pragma unroll
    for (int ni=0;ni<4;ni++){
        int row = m0 + wm*32 + mi*16 + gr;
        int col = wn*32 + ni*8 + c2;
        float2 bb = *(const float2*)(bias + col);
        float2 v0 = {acc[mi][ni][0]+bb.x, acc[mi][ni][1]+bb.y};
        float2 v1 = {acc[mi][ni][2]+bb.x, acc[mi][ni][3]+bb.y};
        *(float2*)(out + (size_t)row*HD + col) = v0;
        *(float2*)(out + (size_t)(row+8)*HD + col) = v1;
    }
}

// ---------------------------------------------------------------------------
extern "C" void kernel_launch(void* const* d_in, const int* in_sizes, int n_in,
                              void* d_out, int out_size) {
    const float* q  = (const float*)d_in[0];
    const float* k  = (const float*)d_in[1];
    const float* v  = (const float*)d_in[2];
    const float* wq = (const float*)d_in[3];
    const float* bq = (const float*)d_in[4];
    const float* wk = (const float*)d_in[5];
    const float* bk = (const float*)d_in[6];
    const float* wv = (const float*)d_in[7];
    const float* bv = (const float*)d_in[8];
    const float* wp = (const float*)d_in[9];
    const float* bp = (const float*)d_in[10];

    float* out  = (float*)d_out;
    float* attn = out + OUT_ELEMS;

    dim3 projGrid(NH, (BATCH*SEQ)/128, 3);            // (8, 32, 3)
    proj_all_kernel<<<projGrid, 256>>>(q, k, v, wq, wk, wv, bq, bk, bv);

    dim3 scoreGrid(SEQ/128, SEQ/128, BH);             // (8, 8, 32)
    scores_exp_kernel<<<scoreGrid, 512>>>(attn);

    rowsum_kernel<<<NROWS/256, 256>>>();

    dim3 ctxGrid(SEQ/64, BH, QCHUNKS);                // (16, 32, 4)
    context_norm_kernel<<<ctxGrid, 256>>>(attn);

    outproj_kernel<<<(BATCH*SEQ)/128, 256>>>(wp, bp, out);
}

// round 9
// speedup vs baseline: 1.0837x; 1.0344x over previous
#include <cuda_runtime.h>
#include <cuda_bf16.h>
#include <math.h>
#include <stdint.h>

#define BATCH 4
#define SEQ   1024
#define QDIM  512
#define NH    8
#define HD    64
#define BH    (BATCH*NH)
#define OUT_ELEMS  (BATCH*SEQ*HD)
#define PROJ_ELEMS (BATCH*NH*SEQ*HD)
#define NROWS (BH*SEQ)
#define QCHUNKS 4
#define STR 20   // smem row stride in words (80B: 16B-aligned rows for ldmatrix)

__device__ float g_q[PROJ_ELEMS];
__device__ float g_k[PROJ_ELEMS];
__device__ float g_v[PROJ_ELEMS];
__device__ float g_cpart[QCHUNKS*PROJ_ELEMS];
__device__ float g_partial[NROWS * 8];
__device__ float g_rinv[NROWS];

// ---------------------------------------------------------------------------
// bf16 split helpers
// ---------------------------------------------------------------------------
__device__ __forceinline__ uint32_t packbf(float x, float y){
    __nv_bfloat162 t = __floats2bfloat162_rn(x, y);
    return *(uint32_t*)&t;
}
__device__ __forceinline__ void packsplit(float x, float y, uint32_t& hi, uint32_t& lo){
    __nv_bfloat16 xh = __float2bfloat16_rn(x);
    __nv_bfloat16 yh = __float2bfloat16_rn(y);
    __nv_bfloat162 h; h.x = xh; h.y = yh;
    hi = *(uint32_t*)&h;
    lo = packbf(x - __bfloat162float(xh), y - __bfloat162float(yh));
}
__device__ __forceinline__ void mmabf(float c[4], const uint32_t a[4], const uint32_t b[2]){
    asm volatile("mma.sync.aligned.m16n8k16.row.col.f32.bf16.bf16.f32 "
        "{%0,%1,%2,%3},{%4,%5,%6,%7},{%8,%9},{%0,%1,%2,%3};"
        : "+f"(c[0]),"+f"(c[1]),"+f"(c[2]),"+f"(c[3])
        : "r"(a[0]),"r"(a[1]),"r"(a[2]),"r"(a[3]),"r"(b[0]),"r"(b[1]));
}

__device__ __forceinline__ uint32_t smem_u32(const void* p){
    uint32_t a;
    asm("{.reg .u64 t; cvta.to.shared.u64 t, %1; cvt.u32.u64 %0, t;}" : "=r"(a) : "l"(p));
    return a;
}
// A-fragment (m16 x k16) via ldmatrix.x4. S: bf16x2 words, rows stride STR words.
__device__ __forceinline__ void ldsmA(const uint32_t* S, int row0, int kp, uint32_t a[4]){
    int lane = threadIdx.x & 31;
    const uint32_t* p = S + (row0 + (lane & 15))*STR + kp + ((lane >> 4) << 2);
    uint32_t addr = smem_u32(p);
    asm volatile("ldmatrix.sync.aligned.m8n8.x4.shared.b16 {%0,%1,%2,%3}, [%4];"
        : "=r"(a[0]),"=r"(a[1]),"=r"(a[2]),"=r"(a[3]) : "r"(addr));
}
// B-fragments for TWO adjacent n8 groups (n0, n0+8) via one ldmatrix.x4.
__device__ __forceinline__ void ldsmB2(const uint32_t* S, int n0, int kp,
                                       uint32_t b0[2], uint32_t b1[2]){
    int lane = threadIdx.x & 31;
    int row = n0 + ((lane >> 4) << 3) + (lane & 7);
    int ko  = kp + (((lane >> 3) & 1) << 2);
    uint32_t addr = smem_u32(S + row*STR + ko);
    asm volatile("ldmatrix.sync.aligned.m8n8.x4.shared.b16 {%0,%1,%2,%3}, [%4];"
        : "=r"(b0[0]),"=r"(b0[1]),"=r"(b1[0]),"=r"(b1[1]) : "r"(addr));
}

// ---------------------------------------------------------------------------
// Kernel 1: all three projections  Y = X @ W^T + b  (3-term bf16) -> [b,h,l,d]
// ---------------------------------------------------------------------------
__global__ __launch_bounds__(256) void proj_all_kernel(
        const float* __restrict__ x0, const float* __restrict__ x1, const float* __restrict__ x2,
        const float* __restrict__ w0, const float* __restrict__ w1, const float* __restrict__ w2,
        const float* __restrict__ b0, const float* __restrict__ b1, const float* __restrict__ b2){
    __shared__ __align__(16) uint32_t Xhi[128*STR], Xlo[128*STR];
    __shared__ __align__(16) uint32_t Whi[64*STR],  Wlo[64*STR];
    int sel = blockIdx.z;
    const float* X = sel==0 ? x0 : sel==1 ? x1 : x2;
    const float* W = sel==0 ? w0 : sel==1 ? w1 : w2;
    const float* bias = sel==0 ? b0 : sel==1 ? b1 : b2;
    float* dst = sel==0 ? g_q : sel==1 ? g_k : g_v;

    int tid = threadIdx.x;
    int h = blockIdx.x, n0 = h*64;
    int m0 = blockIdx.y*128;
    int w = tid>>5, wm = w>>1, wn = w&1;
    int lane = tid&31, gr = lane>>2, c2 = (lane&3)*2;

    float acc[2][4][4] = {};
    for (int k0=0; k0<QDIM; k0+=32){
        __syncthreads();
        #pragma unroll
        for (int i=0;i<4;i++){
            int lin = tid + i*256;
            int r = lin>>3, c4 = lin&7;
            float4 xv = *(const float4*)(X + (size_t)(m0+r)*QDIM + k0 + c4*4);
            uint32_t h0,l0,h1,l1;
            packsplit(xv.x, xv.y, h0, l0);
            packsplit(xv.z, xv.w, h1, l1);
            Xhi[r*STR + c4*2]   = h0; Xhi[r*STR + c4*2+1] = h1;
            Xlo[r*STR + c4*2]   = l0; Xlo[r*STR + c4*2+1] = l1;
        }
        #pragma unroll
        for (int i=0;i<2;i++){
            int lin = tid + i*256;
            int r = lin>>3, c4 = lin&7;
            float4 wv = *(const float4*)(W + (size_t)(n0+r)*QDIM + k0 + c4*4);
            uint32_t h0,l0,h1,l1;
            packsplit(wv.x, wv.y, h0, l0);
            packsplit(wv.z, wv.w, h1, l1);
            Whi[r*STR + c4*2]   = h0; Whi[r*STR + c4*2+1] = h1;
            Wlo[r*STR + c4*2]   = l0; Wlo[r*STR + c4*2+1] = l1;
        }
        __syncthreads();
        #pragma unroll
        for (int ks=0; ks<2; ks++){
            int kp = ks*8;
            uint32_t ah[2][4], al[2][4];
            #pragma unroll
            for (int mi=0;mi<2;mi++){
                ldsmA(Xhi, wm*32+mi*16, kp, ah[mi]);
                ldsmA(Xlo, wm*32+mi*16, kp, al[mi]);
            }
            #pragma unroll
            for (int nj=0;nj<2;nj++){
                uint32_t bh0[2], bh1[2], bl0[2], bl1[2];
                ldsmB2(Whi, wn*32+nj*16, kp, bh0, bh1);
                ldsmB2(Wlo, wn*32+nj*16, kp, bl0, bl1);
                #pragma unroll
                for (int mi=0;mi<2;mi++){
                    mmabf(acc[mi][nj*2],   ah[mi], bh0);
                    mmabf(acc[mi][nj*2],   ah[mi], bl0);
                    mmabf(acc[mi][nj*2],   al[mi], bh0);
                    mmabf(acc[mi][nj*2+1], ah[mi], bh1);
                    mmabf(acc[mi][nj*2+1], ah[mi], bl1);
                    mmabf(acc[mi][nj*2+1], al[mi], bh1);
                }
            }
        }
    }
    int b = m0>>10, l0 = m0&1023;
    float* base = dst + (size_t)(b*NH+h)*SEQ*HD;
    #pragma unroll
    for (int mi=0;mi<2;mi++)
    #pragma unroll
    for (int ni=0;ni<4;ni++){
        int row = l0 + wm*32 + mi*16 + gr;
        int col = wn*32 + ni*8 + c2;
        float2 bb = *(const float2*)(bias + n0 + col);
        float2 v0 = {acc[mi][ni][0]+bb.x, acc[mi][ni][1]+bb.y};
        float2 v1 = {acc[mi][ni][2]+bb.x, acc[mi][ni][3]+bb.y};
        *(float2*)(base + (size_t)row*HD + col) = v0;
        *(float2*)(base + (size_t)(row+8)*HD + col) = v1;
    }
}

// ---------------------------------------------------------------------------
// Kernel 2: P = exp(0.5 * Q K^T) (3-term bf16) -> attn (unnormalized) + partials
// grid (8 kb, 8 qb, 32 bh), 512 threads, tile 128q x 128k, warp 32x32
// ---------------------------------------------------------------------------
__global__ __launch_bounds__(512) void scores_exp_kernel(float* __restrict__ attn){
    __shared__ __align__(16) uint32_t Qhi[128*STR], Qlo[128*STR];
    __shared__ __align__(16) uint32_t Khi[128*STR], Klo[128*STR];
    __shared__ float sums[128][4];

    int tid = threadIdx.x;
    int kb = blockIdx.x, q0b = blockIdx.y*128, bh = blockIdx.z;
    int w = tid>>5, wq = w>>2, wk = w&3;
    int lane = tid&31, gr = lane>>2, c2 = (lane&3)*2;
    const float* Qg = g_q + (size_t)(bh*SEQ + q0b)*HD;
    const float* Kg = g_k + (size_t)(bh*SEQ + kb*128)*HD;

    float acc[2][4][4] = {};
    #pragma unroll
    for (int dt=0; dt<2; dt++){
        int d0 = dt*32;
        __syncthreads();
        #pragma unroll
        for (int i=0;i<2;i++){
            int lin = tid + i*512;
            int r = lin>>3, c4 = lin&7;
            float4 xq = *(const float4*)(Qg + (size_t)r*HD + d0 + c4*4);
            float4 xk = *(const float4*)(Kg + (size_t)r*HD + d0 + c4*4);
            uint32_t h0,l0,h1,l1;
            packsplit(xq.x, xq.y, h0, l0); packsplit(xq.z, xq.w, h1, l1);
            Qhi[r*STR + c4*2] = h0; Qhi[r*STR + c4*2+1] = h1;
            Qlo[r*STR + c4*2] = l0; Qlo[r*STR + c4*2+1] = l1;
            packsplit(xk.x, xk.y, h0, l0); packsplit(xk.z, xk.w, h1, l1);
            Khi[r*STR + c4*2] = h0; Khi[r*STR + c4*2+1] = h1;
            Klo[r*STR + c4*2] = l0; Klo[r*STR + c4*2+1] = l1;
        }
        __syncthreads();
        #pragma unroll
        for (int ks=0; ks<2; ks++){
            int kp = ks*8;
            uint32_t ah[2][4], al[2][4];
            #pragma unroll
            for (int mi=0;mi<2;mi++){
                ldsmA(Qhi, wq*32+mi*16, kp, ah[mi]);
                ldsmA(Qlo, wq*32+mi*16, kp, al[mi]);
            }
            #pragma unroll
            for (int nj=0;nj<2;nj++){
                uint32_t bh0[2], bh1[2], bl0[2], bl1[2];
                ldsmB2(Khi, wk*32+nj*16, kp, bh0, bh1);
                ldsmB2(Klo, wk*32+nj*16, kp, bl0, bl1);
                #pragma unroll
                for (int mi=0;mi<2;mi++){
                    mmabf(acc[mi][nj*2],   ah[mi], bh0);
                    mmabf(acc[mi][nj*2],   ah[mi], bl0);
                    mmabf(acc[mi][nj*2],   al[mi], bh0);
                    mmabf(acc[mi][nj*2+1], ah[mi], bh1);
                    mmabf(acc[mi][nj*2+1], ah[mi], bl1);
                    mmabf(acc[mi][nj*2+1], al[mi], bh1);
                }
            }
        }
    }

    float* Ab = attn + (size_t)bh*SEQ*SEQ;
    float rs[2][2] = {};
    #pragma unroll
    for (int mi=0;mi<2;mi++)
    #pragma unroll
    for (int ni=0;ni<4;ni++){
        float e0 = __expf(acc[mi][ni][0]*0.5f);
        float e1 = __expf(acc[mi][ni][1]*0.5f);
        float e2 = __expf(acc[mi][ni][2]*0.5f);
        float e3 = __expf(acc[mi][ni][3]*0.5f);
        int row = q0b + wq*32 + mi*16 + gr;
        int col = kb*128 + wk*32 + ni*8 + c2;
        float2 v0 = {e0, e1}, v1 = {e2, e3};
        *(float2*)(Ab + (size_t)row*SEQ + col) = v0;
        *(float2*)(Ab + (size_t)(row+8)*SEQ + col) = v1;
        rs[mi][0] += e0 + e1;
        rs[mi][1] += e2 + e3;
    }
    #pragma unroll
    for (int mi=0;mi<2;mi++)
    #pragma unroll
    for (int j=0;j<2;j++){
        float s = rs[mi][j];
        s += __shfl_xor_sync(0xffffffffu, s, 1);
        s += __shfl_xor_sync(0xffffffffu, s, 2);
        rs[mi][j] = s;
    }
    if ((lane&3)==0){
        #pragma unroll
        for (int mi=0;mi<2;mi++)
        #pragma unroll
        for (int j=0;j<2;j++)
            sums[wq*32 + mi*16 + gr + j*8][wk] = rs[mi][j];
    }
    __syncthreads();
    if (tid < 128){
        float t = sums[tid][0] + sums[tid][1] + sums[tid][2] + sums[tid][3];
        g_partial[(((size_t)bh*SEQ + q0b + tid)<<3) + kb] = t;
    }
}

// ---------------------------------------------------------------------------
// Kernel 3: row-sum reduce -> 1/S
// ---------------------------------------------------------------------------
__global__ __launch_bounds__(256) void rowsum_kernel(){
    int r = blockIdx.x*256 + threadIdx.x;
    const float* p = g_partial + ((size_t)r<<3);
    float s = ((p[0]+p[1])+(p[2]+p[3])) + ((p[4]+p[5])+(p[6]+p[7]));
    g_rinv[r] = 1.0f / s;
}

// ---------------------------------------------------------------------------
// Kernel 4: normalize attn in place + PARTIAL context (3-term bf16)
// grid (16 n-tiles of 64, 32 bh, 4 q-chunks), 256 threads, pipelined.
// ---------------------------------------------------------------------------
__global__ __launch_bounds__(256) void context_norm_kernel(float* __restrict__ attn){
    __shared__ __align__(16) uint32_t Vhi[64*STR], Vlo[64*STR];
    __shared__ __align__(16) uint32_t Ahi[64*STR], Alo[64*STR];
    int tid = threadIdx.x;
    int nb = blockIdx.x*64, bh = blockIdx.y, qc = blockIdx.z;
    int w = tid>>5, wm = w>>1, wn = w&1;   // wm: 4 x m16 (d), wn: 2 x n32
    int lane = tid&31, gr = lane>>2, tc = lane&3;
    float* Ag = attn + (size_t)bh*SEQ*SEQ + nb;
    const float* Vg = g_v + (size_t)bh*SEQ*HD;
    const float* rinv = g_rinv + (size_t)bh*SEQ;

    int ac4 = tid & 15, aqp = tid >> 4;
    float vr[4][2];
    float4 ar0, ar1; float ri0, ri1;

    #define CTX_LOADV(Q0)                                             \
        _Pragma("unroll")                                             \
        for (int i=0;i<4;i++){                                        \
            int p = tid + i*256; int d = p & 63, qp = p >> 6;         \
            vr[i][0] = Vg[(size_t)((Q0)+2*qp)*HD + d];                \
            vr[i][1] = Vg[(size_t)((Q0)+2*qp+1)*HD + d];              \
        }
    #define CTX_LOADA(Q0) {                                           \
        size_t o0 = (size_t)((Q0)+2*aqp)*SEQ + ac4*4;                 \
        ar0 = *(const float4*)(Ag + o0);                              \
        ar1 = *(const float4*)(Ag + o0 + SEQ);                        \
        ri0 = rinv[(Q0)+2*aqp]; ri1 = rinv[(Q0)+2*aqp+1];             \
    }

    float acc[4][4] = {};
    int qlo = qc*(SEQ/QCHUNKS), qhi_ = qlo + SEQ/QCHUNKS;
    CTX_LOADV(qlo);
    CTX_LOADA(qlo);
    for (int q0=qlo; q0<qhi_; q0+=32){
        #pragma unroll
        for (int i=0;i<4;i++){
            int p = tid + i*256; int d = p & 63, qp = p >> 6;
            uint32_t hh, ll; packsplit(vr[i][0], vr[i][1], hh, ll);
            Vhi[d*STR+qp] = hh; Vlo[d*STR+qp] = ll;
        }
        {
            float4 a0 = ar0, a1 = ar1;
            a0.x*=ri0; a0.y*=ri0; a0.z*=ri0; a0.w*=ri0;
            a1.x*=ri1; a1.y*=ri1; a1.z*=ri1; a1.w*=ri1;
            size_t o0 = (size_t)(q0+2*aqp)*SEQ + ac4*4;
            *(float4*)(Ag + o0) = a0;
            *(float4*)(Ag + o0 + SEQ) = a1;
            uint32_t hh, ll;
            packsplit(a0.x, a1.x, hh, ll); Ahi[(ac4*4+0)*STR+aqp]=hh; Alo[(ac4*4+0)*STR+aqp]=ll;
            packsplit(a0.y, a1.y, hh, ll); Ahi[(ac4*4+1)*STR+aqp]=hh; Alo[(ac4*4+1)*STR+aqp]=ll;
            packsplit(a0.z, a1.z, hh, ll); Ahi[(ac4*4+2)*STR+aqp]=hh; Alo[(ac4*4+2)*STR+aqp]=ll;
            packsplit(a0.w, a1.w, hh, ll); Ahi[(ac4*4+3)*STR+aqp]=hh; Alo[(ac4*4+3)*STR+aqp]=ll;
        }
        __syncthreads();
        if (q0+32 < qhi_){
            CTX_LOADV(q0+32);
            CTX_LOADA(q0+32);
        }
        #pragma unroll
        for (int ks=0; ks<2; ks++){
            int kp = ks*8;
            uint32_t ah[4], al[4];
            ldsmA(Vhi, wm*16, kp, ah);
            ldsmA(Vlo, wm*16, kp, al);
            #pragma unroll
            for (int nj=0;nj<2;nj++){
                uint32_t bh0[2], bh1[2], bl0[2], bl1[2];
                ldsmB2(Ahi, wn*32+nj*16, kp, bh0, bh1);
                ldsmB2(Alo, wn*32+nj*16, kp, bl0, bl1);
                mmabf(acc[nj*2],   ah, bh0);
                mmabf(acc[nj*2],   ah, bl0);
                mmabf(acc[nj*2],   al, bh0);
                mmabf(acc[nj*2+1], ah, bh1);
                mmabf(acc[nj*2+1], ah, bl1);
                mmabf(acc[nj*2+1], al, bh1);
            }
        }
        __syncthreads();
    }
    #undef CTX_LOADV
    #undef CTX_LOADA

    float* Cb = g_cpart + (size_t)qc*PROJ_ELEMS + (size_t)bh*SEQ*HD;
    #pragma unroll
    for (int ni=0;ni<4;ni++){
        int drow = wm*16 + gr;
        int col  = nb + wn*32 + ni*8 + tc*2;
        Cb[(size_t)col*HD + drow]         = acc[ni][0];
        Cb[(size_t)(col+1)*HD + drow]     = acc[ni][1];
        Cb[(size_t)col*HD + drow+8]       = acc[ni][2];
        Cb[(size_t)(col+1)*HD + drow+8]   = acc[ni][3];
    }
}

// ---------------------------------------------------------------------------
// Kernel 5: output = (sum of 4 ctx partials) @ wp^T + bp   (3-term bf16)
// ---------------------------------------------------------------------------
__global__ __launch_bounds__(256) void outproj_kernel(const float* __restrict__ W,
        const float* __restrict__ bias, float* __restrict__ out){
    __shared__ __align__(16) uint32_t Chi[128*STR], Clo[128*STR];
    __shared__ __align__(16) uint32_t Whi[64*STR],  Wlo[64*STR];
    int tid = threadIdx.x;
    int m0 = blockIdx.x*128;
    int b = m0>>10, l0 = m0&1023;
    int w = tid>>5, wm = w>>1, wn = w&1;
    int lane = tid&31, gr = lane>>2, c2 = (lane&3)*2;

    float acc[2][4][4] = {};
    for (int k0=0; k0<QDIM; k0+=32){
        int h = k0>>6, off = k0&63;
        const float* Cg = g_cpart + ((size_t)(b*NH+h)*SEQ + l0)*HD + off;
        __syncthreads();
        #pragma unroll
        for (int i=0;i<4;i++){
            int lin = tid + i*256;
            int r = lin>>3, c4 = lin&7;
            size_t o = (size_t)r*HD + c4*4;
            float4 a0 = *(const float4*)(Cg + o);
            float4 a1 = *(const float4*)(Cg + (size_t)PROJ_ELEMS + o);
            float4 a2 = *(const float4*)(Cg + (size_t)2*PROJ_ELEMS + o);
            float4 a3 = *(const float4*)(Cg + (size_t)3*PROJ_ELEMS + o);
            float4 s;
            s.x = (a0.x+a1.x)+(a2.x+a3.x);
            s.y = (a0.y+a1.y)+(a2.y+a3.y);
            s.z = (a0.z+a1.z)+(a2.z+a3.z);
            s.w = (a0.w+a1.w)+(a2.w+a3.w);
            uint32_t h0,l0_,h1,l1;
            packsplit(s.x, s.y, h0, l0_);
            packsplit(s.z, s.w, h1, l1);
            Chi[r*STR + c4*2] = h0; Chi[r*STR + c4*2+1] = h1;
            Clo[r*STR + c4*2] = l0_; Clo[r*STR + c4*2+1] = l1;
        }
        #pragma unroll
        for (int i=0;i<2;i++){
            int lin = tid + i*256;
            int r = lin>>3, c4 = lin&7;
            float4 wv = *(const float4*)(W + (size_t)r*QDIM + k0 + c4*4);
            uint32_t h0,l0_,h1,l1;
            packsplit(wv.x, wv.y, h0, l0_);
            packsplit(wv.z, wv.w, h1, l1);
            Whi[r*STR + c4*2] = h0; Whi[r*STR + c4*2+1] = h1;
            Wlo[r*STR + c4*2] = l0_; Wlo[r*STR + c4*2+1] = l1;
        }
        __syncthreads();
        #pragma unroll
        for (int ks=0; ks<2; ks++){
            int kp = ks*8;
            uint32_t ah[2][4], al[2][4];
            #pragma unroll
            for (int mi=0;mi<2;mi++){
                ldsmA(Chi, wm*32+mi*16, kp, ah[mi]);
                ldsmA(Clo, wm*32+mi*16, kp, al[mi]);
            }
            #pragma unroll
            for (int nj=0;nj<2;nj++){
                uint32_t bh0[2], bh1[2], bl0[2], bl1[2];
                ldsmB2(Whi, wn*32+nj*16, kp, bh0, bh1);
                ldsmB2(Wlo, wn*32+nj*16, kp, bl0, bl1);
                #pragma unroll
                for (int mi=0;mi<2;mi++){
                    mmabf(acc[mi][nj*2],   ah[mi], bh0);
                    mmabf(acc[mi][nj*2],   ah[mi], bl0);
                    mmabf(acc[mi][nj*2],   al[mi], bh0);
                    mmabf(acc[mi][nj*2+1], ah[mi], bh1);
                    mmabf(acc[mi][nj*2+1], ah[mi], bl1);
                    mmabf(acc[mi][nj*2+1], al[mi], bh1);
                }
            }
        }
    }
    #pragma unroll
    for (int mi=0;mi<2;mi++)
    #pragma unroll
    for (int ni=0;ni<4;ni++){
        int row = m0 + wm*32 + mi*16 + gr;
        int col = wn*32 + ni*8 + c2;
        float2 bb = *(const float2*)(bias + col);
        float2 v0 = {acc[mi][ni][0]+bb.x, acc[mi][ni][1]+bb.y};
        float2 v1 = {acc[mi][ni][2]+bb.x, acc[mi][ni][3]+bb.y};
        *(float2*)(out + (size_t)row*HD + col) = v0;
        *(float2*)(out + (size_t)(row+8)*HD + col) = v1;
    }
}

// ---------------------------------------------------------------------------
extern "C" void kernel_launch(void* const* d_in, const int* in_sizes, int n_in,
                              void* d_out, int out_size) {
    const float* q  = (const float*)d_in[0];
    const float* k  = (const float*)d_in[1];
    const float* v  = (const float*)d_in[2];
    const float* wq = (const float*)d_in[3];
    const float* bq = (const float*)d_in[4];
    const float* wk = (const float*)d_in[5];
    const float* bk = (const float*)d_in[6];
    const float* wv = (const float*)d_in[7];
    const float* bv = (const float*)d_in[8];
    const float* wp = (const float*)d_in[9];
    const float* bp = (const float*)d_in[10];

    float* out  = (float*)d_out;
    float* attn = out + OUT_ELEMS;

    dim3 projGrid(NH, (BATCH*SEQ)/128, 3);            // (8, 32, 3)
    proj_all_kernel<<<projGrid, 256>>>(q, k, v, wq, wk, wv, bq, bk, bv);

    dim3 scoreGrid(SEQ/128, SEQ/128, BH);             // (8, 8, 32)
    scores_exp_kernel<<<scoreGrid, 512>>>(attn);

    rowsum_kernel<<<NROWS/256, 256>>>();

    dim3 ctxGrid(SEQ/64, BH, QCHUNKS);                // (16, 32, 4)
    context_norm_kernel<<<ctxGrid, 256>>>(attn);

    outproj_kernel<<<(BATCH*SEQ)/128, 256>>>(wp, bp, out);
}

// round 10
// speedup vs baseline: 1.2023x; 1.1094x over previous
#include <cuda_runtime.h>
#include <cuda_bf16.h>
#include <math.h>
#include <stdint.h>

#define BATCH 4
#define SEQ   1024
#define QDIM  512
#define NH    8
#define HD    64
#define BH    (BATCH*NH)
#define OUT_ELEMS  (BATCH*SEQ*HD)
#define PROJ_ELEMS (BATCH*NH*SEQ*HD)
#define NROWS (BH*SEQ)
#define QCHUNKS 4
#define STR 20    // k-pair-major smem row stride (words): proj/scores/outproj
#define TSTR 36   // natural-orientation smem row stride (words): context trans tiles

__device__ float g_q[PROJ_ELEMS];
__device__ float g_k[PROJ_ELEMS];
__device__ float g_v[PROJ_ELEMS];
__device__ float g_cpart[QCHUNKS*PROJ_ELEMS];
__device__ float g_partial[NROWS * 8];
__device__ float g_rinv[NROWS];

// ---------------------------------------------------------------------------
// bf16 split helpers
// ---------------------------------------------------------------------------
__device__ __forceinline__ uint32_t packbf(float x, float y){
    __nv_bfloat162 t = __floats2bfloat162_rn(x, y);
    return *(uint32_t*)&t;
}
__device__ __forceinline__ void packsplit(float x, float y, uint32_t& hi, uint32_t& lo){
    __nv_bfloat16 xh = __float2bfloat16_rn(x);
    __nv_bfloat16 yh = __float2bfloat16_rn(y);
    __nv_bfloat162 h; h.x = xh; h.y = yh;
    hi = *(uint32_t*)&h;
    lo = packbf(x - __bfloat162float(xh), y - __bfloat162float(yh));
}
__device__ __forceinline__ void mmabf(float c[4], const uint32_t a[4], const uint32_t b[2]){
    asm volatile("mma.sync.aligned.m16n8k16.row.col.f32.bf16.bf16.f32 "
        "{%0,%1,%2,%3},{%4,%5,%6,%7},{%8,%9},{%0,%1,%2,%3};"
        : "+f"(c[0]),"+f"(c[1]),"+f"(c[2]),"+f"(c[3])
        : "r"(a[0]),"r"(a[1]),"r"(a[2]),"r"(a[3]),"r"(b[0]),"r"(b[1]));
}

__device__ __forceinline__ uint32_t smem_u32(const void* p){
    uint32_t a;
    asm("{.reg .u64 t; cvta.to.shared.u64 t, %1; cvt.u32.u64 %0, t;}" : "=r"(a) : "l"(p));
    return a;
}
// ---- k-pair-major (non-trans) loaders, stride STR ----
__device__ __forceinline__ void ldsmA(const uint32_t* S, int row0, int kp, uint32_t a[4]){
    int lane = threadIdx.x & 31;
    const uint32_t* p = S + (row0 + (lane & 15))*STR + kp + ((lane >> 4) << 2);
    uint32_t addr = smem_u32(p);
    asm volatile("ldmatrix.sync.aligned.m8n8.x4.shared.b16 {%0,%1,%2,%3}, [%4];"
        : "=r"(a[0]),"=r"(a[1]),"=r"(a[2]),"=r"(a[3]) : "r"(addr));
}
__device__ __forceinline__ void ldsmB2(const uint32_t* S, int n0, int kp,
                                       uint32_t b0[2], uint32_t b1[2]){
    int lane = threadIdx.x & 31;
    int row = n0 + ((lane >> 4) << 3) + (lane & 7);
    int ko  = kp + (((lane >> 3) & 1) << 2);
    uint32_t addr = smem_u32(S + row*STR + ko);
    asm volatile("ldmatrix.sync.aligned.m8n8.x4.shared.b16 {%0,%1,%2,%3}, [%4];"
        : "=r"(b0[0]),"=r"(b0[1]),"=r"(b1[0]),"=r"(b1[1]) : "r"(addr));
}
// ---- natural-orientation (trans) loaders, stride TSTR; memory rows = k ----
// A-operand (m16k16) from [k][m] bf16 rows
__device__ __forceinline__ void ldsmAT(const uint32_t* S, int k0, int m0, uint32_t a[4]){
    int lane = threadIdx.x & 31;
    int row  = k0 + (lane & 7) + ((lane & 16) >> 1);
    int woff = (m0 >> 1) + ((lane & 8) >> 1);
    uint32_t addr = smem_u32(S + row*TSTR + woff);
    asm volatile("ldmatrix.sync.aligned.m8n8.x4.trans.shared.b16 {%0,%1,%2,%3}, [%4];"
        : "=r"(a[0]),"=r"(a[1]),"=r"(a[2]),"=r"(a[3]) : "r"(addr));
}
// B-operands for n0 and n0+8 (k16 each) from [k][n] bf16 rows
__device__ __forceinline__ void ldsmBT2(const uint32_t* S, int k0, int n0,
                                        uint32_t b0[2], uint32_t b1[2]){
    int lane = threadIdx.x & 31;
    int row  = k0 + (lane & 7) + (lane & 8);
    int woff = (n0 >> 1) + ((lane & 16) >> 2);
    uint32_t addr = smem_u32(S + row*TSTR + woff);
    asm volatile("ldmatrix.sync.aligned.m8n8.x4.trans.shared.b16 {%0,%1,%2,%3}, [%4];"
        : "=r"(b0[0]),"=r"(b0[1]),"=r"(b1[0]),"=r"(b1[1]) : "r"(addr));
}

// ---------------------------------------------------------------------------
// Kernel 1: all three projections  Y = X @ W^T + b  (3-term bf16) -> [b,h,l,d]
// ---------------------------------------------------------------------------
__global__ __launch_bounds__(256) void proj_all_kernel(
        const float* __restrict__ x0, const float* __restrict__ x1, const float* __restrict__ x2,
        const float* __restrict__ w0, const float* __restrict__ w1, const float* __restrict__ w2,
        const float* __restrict__ b0, const float* __restrict__ b1, const float* __restrict__ b2){
    __shared__ __align__(16) uint32_t Xhi[128*STR], Xlo[128*STR];
    __shared__ __align__(16) uint32_t Whi[64*STR],  Wlo[64*STR];
    int sel = blockIdx.z;
    const float* X = sel==0 ? x0 : sel==1 ? x1 : x2;
    const float* W = sel==0 ? w0 : sel==1 ? w1 : w2;
    const float* bias = sel==0 ? b0 : sel==1 ? b1 : b2;
    float* dst = sel==0 ? g_q : sel==1 ? g_k : g_v;

    int tid = threadIdx.x;
    int h = blockIdx.x, n0 = h*64;
    int m0 = blockIdx.y*128;
    int w = tid>>5, wm = w>>1, wn = w&1;
    int lane = tid&31, gr = lane>>2, c2 = (lane&3)*2;

    float acc[2][4][4] = {};
    for (int k0=0; k0<QDIM; k0+=32){
        __syncthreads();
        #pragma unroll
        for (int i=0;i<4;i++){
            int lin = tid + i*256;
            int r = lin>>3, c4 = lin&7;
            float4 xv = *(const float4*)(X + (size_t)(m0+r)*QDIM + k0 + c4*4);
            uint32_t h0,l0,h1,l1;
            packsplit(xv.x, xv.y, h0, l0);
            packsplit(xv.z, xv.w, h1, l1);
            Xhi[r*STR + c4*2]   = h0; Xhi[r*STR + c4*2+1] = h1;
            Xlo[r*STR + c4*2]   = l0; Xlo[r*STR + c4*2+1] = l1;
        }
        #pragma unroll
        for (int i=0;i<2;i++){
            int lin = tid + i*256;
            int r = lin>>3, c4 = lin&7;
            float4 wv = *(const float4*)(W + (size_t)(n0+r)*QDIM + k0 + c4*4);
            uint32_t h0,l0,h1,l1;
            packsplit(wv.x, wv.y, h0, l0);
            packsplit(wv.z, wv.w, h1, l1);
            Whi[r*STR + c4*2]   = h0; Whi[r*STR + c4*2+1] = h1;
            Wlo[r*STR + c4*2]   = l0; Wlo[r*STR + c4*2+1] = l1;
        }
        __syncthreads();
        #pragma unroll
        for (int ks=0; ks<2; ks++){
            int kp = ks*8;
            uint32_t ah[2][4], al[2][4];
            #pragma unroll
            for (int mi=0;mi<2;mi++){
                ldsmA(Xhi, wm*32+mi*16, kp, ah[mi]);
                ldsmA(Xlo, wm*32+mi*16, kp, al[mi]);
            }
            #pragma unroll
            for (int nj=0;nj<2;nj++){
                uint32_t bh0[2], bh1[2], bl0[2], bl1[2];
                ldsmB2(Whi, wn*32+nj*16, kp, bh0, bh1);
                ldsmB2(Wlo, wn*32+nj*16, kp, bl0, bl1);
                #pragma unroll
                for (int mi=0;mi<2;mi++){
                    mmabf(acc[mi][nj*2],   ah[mi], bh0);
                    mmabf(acc[mi][nj*2],   ah[mi], bl0);
                    mmabf(acc[mi][nj*2],   al[mi], bh0);
                    mmabf(acc[mi][nj*2+1], ah[mi], bh1);
                    mmabf(acc[mi][nj*2+1], ah[mi], bl1);
                    mmabf(acc[mi][nj*2+1], al[mi], bh1);
                }
            }
        }
    }
    int b = m0>>10, l0 = m0&1023;
    float* base = dst + (size_t)(b*NH+h)*SEQ*HD;
    #pragma unroll
    for (int mi=0;mi<2;mi++)
    #pragma unroll
    for (int ni=0;ni<4;ni++){
        int row = l0 + wm*32 + mi*16 + gr;
        int col = wn*32 + ni*8 + c2;
        float2 bb = *(const float2*)(bias + n0 + col);
        float2 v0 = {acc[mi][ni][0]+bb.x, acc[mi][ni][1]+bb.y};
        float2 v1 = {acc[mi][ni][2]+bb.x, acc[mi][ni][3]+bb.y};
        *(float2*)(base + (size_t)row*HD + col) = v0;
        *(float2*)(base + (size_t)(row+8)*HD + col) = v1;
    }
}

// ---------------------------------------------------------------------------
// Kernel 2: P = exp(0.5 * Q K^T) (3-term bf16) -> attn (unnormalized) + partials
// grid (8 kb, 8 qb, 32 bh), 512 threads, tile 128q x 128k, warp 32x32
// ---------------------------------------------------------------------------
__global__ __launch_bounds__(512) void scores_exp_kernel(float* __restrict__ attn){
    __shared__ __align__(16) uint32_t Qhi[128*STR], Qlo[128*STR];
    __shared__ __align__(16) uint32_t Khi[128*STR], Klo[128*STR];
    __shared__ float sums[128][4];

    int tid = threadIdx.x;
    int kb = blockIdx.x, q0b = blockIdx.y*128, bh = blockIdx.z;
    int w = tid>>5, wq = w>>2, wk = w&3;
    int lane = tid&31, gr = lane>>2, c2 = (lane&3)*2;
    const float* Qg = g_q + (size_t)(bh*SEQ + q0b)*HD;
    const float* Kg = g_k + (size_t)(bh*SEQ + kb*128)*HD;

    float acc[2][4][4] = {};
    #pragma unroll
    for (int dt=0; dt<2; dt++){
        int d0 = dt*32;
        __syncthreads();
        #pragma unroll
        for (int i=0;i<2;i++){
            int lin = tid + i*512;
            int r = lin>>3, c4 = lin&7;
            float4 xq = *(const float4*)(Qg + (size_t)r*HD + d0 + c4*4);
            float4 xk = *(const float4*)(Kg + (size_t)r*HD + d0 + c4*4);
            uint32_t h0,l0,h1,l1;
            packsplit(xq.x, xq.y, h0, l0); packsplit(xq.z, xq.w, h1, l1);
            Qhi[r*STR + c4*2] = h0; Qhi[r*STR + c4*2+1] = h1;
            Qlo[r*STR + c4*2] = l0; Qlo[r*STR + c4*2+1] = l1;
            packsplit(xk.x, xk.y, h0, l0); packsplit(xk.z, xk.w, h1, l1);
            Khi[r*STR + c4*2] = h0; Khi[r*STR + c4*2+1] = h1;
            Klo[r*STR + c4*2] = l0; Klo[r*STR + c4*2+1] = l1;
        }
        __syncthreads();
        #pragma unroll
        for (int ks=0; ks<2; ks++){
            int kp = ks*8;
            uint32_t ah[2][4], al[2][4];
            #pragma unroll
            for (int mi=0;mi<2;mi++){
                ldsmA(Qhi, wq*32+mi*16, kp, ah[mi]);
                ldsmA(Qlo, wq*32+mi*16, kp, al[mi]);
            }
            #pragma unroll
            for (int nj=0;nj<2;nj++){
                uint32_t bh0[2], bh1[2], bl0[2], bl1[2];
                ldsmB2(Khi, wk*32+nj*16, kp, bh0, bh1);
                ldsmB2(Klo, wk*32+nj*16, kp, bl0, bl1);
                #pragma unroll
                for (int mi=0;mi<2;mi++){
                    mmabf(acc[mi][nj*2],   ah[mi], bh0);
                    mmabf(acc[mi][nj*2],   ah[mi], bl0);
                    mmabf(acc[mi][nj*2],   al[mi], bh0);
                    mmabf(acc[mi][nj*2+1], ah[mi], bh1);
                    mmabf(acc[mi][nj*2+1], ah[mi], bl1);
                    mmabf(acc[mi][nj*2+1], al[mi], bh1);
                }
            }
        }
    }

    float* Ab = attn + (size_t)bh*SEQ*SEQ;
    float rs[2][2] = {};
    #pragma unroll
    for (int mi=0;mi<2;mi++)
    #pragma unroll
    for (int ni=0;ni<4;ni++){
        float e0 = __expf(acc[mi][ni][0]*0.5f);
        float e1 = __expf(acc[mi][ni][1]*0.5f);
        float e2 = __expf(acc[mi][ni][2]*0.5f);
        float e3 = __expf(acc[mi][ni][3]*0.5f);
        int row = q0b + wq*32 + mi*16 + gr;
        int col = kb*128 + wk*32 + ni*8 + c2;
        float2 v0 = {e0, e1}, v1 = {e2, e3};
        *(float2*)(Ab + (size_t)row*SEQ + col) = v0;
        *(float2*)(Ab + (size_t)(row+8)*SEQ + col) = v1;
        rs[mi][0] += e0 + e1;
        rs[mi][1] += e2 + e3;
    }
    #pragma unroll
    for (int mi=0;mi<2;mi++)
    #pragma unroll
    for (int j=0;j<2;j++){
        float s = rs[mi][j];
        s += __shfl_xor_sync(0xffffffffu, s, 1);
        s += __shfl_xor_sync(0xffffffffu, s, 2);
        rs[mi][j] = s;
    }
    if ((lane&3)==0){
        #pragma unroll
        for (int mi=0;mi<2;mi++)
        #pragma unroll
        for (int j=0;j<2;j++)
            sums[wq*32 + mi*16 + gr + j*8][wk] = rs[mi][j];
    }
    __syncthreads();
    if (tid < 128){
        float t = sums[tid][0] + sums[tid][1] + sums[tid][2] + sums[tid][3];
        g_partial[(((size_t)bh*SEQ + q0b + tid)<<3) + kb] = t;
    }
}

// ---------------------------------------------------------------------------
// Kernel 3: row-sum reduce -> 1/S
// ---------------------------------------------------------------------------
__global__ __launch_bounds__(256) void rowsum_kernel(){
    int r = blockIdx.x*256 + threadIdx.x;
    const float* p = g_partial + ((size_t)r<<3);
    float s = ((p[0]+p[1])+(p[2]+p[3])) + ((p[4]+p[5])+(p[6]+p[7]));
    g_rinv[r] = 1.0f / s;
}

// ---------------------------------------------------------------------------
// Kernel 4: normalize attn in place + PARTIAL context (3-term bf16)
// grid (16 n-tiles of 64, 32 bh, 4 q-chunks), 256 threads, pipelined.
// Natural-orientation smem tiles ([q][kpos], [q][d]) + ldmatrix.trans:
// pack phase is contiguous STS.64 (conflict-free).
// ---------------------------------------------------------------------------
__global__ __launch_bounds__(256) void context_norm_kernel(float* __restrict__ attn){
    __shared__ __align__(16) uint32_t Vhi[32*TSTR], Vlo[32*TSTR];
    __shared__ __align__(16) uint32_t Ahi[32*TSTR], Alo[32*TSTR];
    int tid = threadIdx.x;
    int nb = blockIdx.x*64, bh = blockIdx.y, qc = blockIdx.z;
    int w = tid>>5, wm = w>>1, wn = w&1;   // wm: 4 x m16 (d), wn: 2 x n32
    int lane = tid&31, gr = lane>>2, tc = lane&3;
    float* Ag = attn + (size_t)bh*SEQ*SEQ + nb;
    const float* Vg = g_v + (size_t)bh*SEQ*HD;
    const float* rinv = g_rinv + (size_t)bh*SEQ;

    // load assignment: i=0..1; idx = tid+i*256; q-row = idx>>4 (0..31); c4 = idx&15
    float4 vr[2], ar[2]; float ri[2];
    #define CTX_LOADS(Q0)                                               \
        _Pragma("unroll")                                               \
        for (int i=0;i<2;i++){                                          \
            int idx = tid + i*256; int r = idx>>4, c4 = idx&15;         \
            vr[i] = *(const float4*)(Vg + (size_t)((Q0)+r)*HD + c4*4);  \
            ar[i] = *(const float4*)(Ag + (size_t)((Q0)+r)*SEQ + c4*4); \
            ri[i] = rinv[(Q0)+r];                                       \
        }

    float acc[4][4] = {};
    int qlo = qc*(SEQ/QCHUNKS), qhi_ = qlo + SEQ/QCHUNKS;
    CTX_LOADS(qlo);
    for (int q0=qlo; q0<qhi_; q0+=32){
        #pragma unroll
        for (int i=0;i<2;i++){
            int idx = tid + i*256; int r = idx>>4, c4 = idx&15;
            uint32_t h0,l0,h1,l1;
            // V pack: natural [q][d] bf16
            packsplit(vr[i].x, vr[i].y, h0, l0);
            packsplit(vr[i].z, vr[i].w, h1, l1);
            *(uint2*)&Vhi[r*TSTR + c4*2] = make_uint2(h0, h1);
            *(uint2*)&Vlo[r*TSTR + c4*2] = make_uint2(l0, l1);
            // A: normalize, write back, pack natural [q][kpos] bf16
            float4 a = ar[i]; float rv = ri[i];
            a.x*=rv; a.y*=rv; a.z*=rv; a.w*=rv;
            *(float4*)(Ag + (size_t)(q0+r)*SEQ + c4*4) = a;
            packsplit(a.x, a.y, h0, l0);
            packsplit(a.z, a.w, h1, l1);
            *(uint2*)&Ahi[r*TSTR + c4*2] = make_uint2(h0, h1);
            *(uint2*)&Alo[r*TSTR + c4*2] = make_uint2(l0, l1);
        }
        __syncthreads();
        if (q0+32 < qhi_){ CTX_LOADS(q0+32); }
        #pragma unroll
        for (int ks=0; ks<2; ks++){
            int k0 = ks*16;
            uint32_t ah[4], al[4];
            ldsmAT(Vhi, k0, wm*16, ah);
            ldsmAT(Vlo, k0, wm*16, al);
            #pragma unroll
            for (int nj=0;nj<2;nj++){
                uint32_t bh0[2], bh1[2], bl0[2], bl1[2];
                ldsmBT2(Ahi, k0, wn*32+nj*16, bh0, bh1);
                ldsmBT2(Alo, k0, wn*32+nj*16, bl0, bl1);
                mmabf(acc[nj*2],   ah, bh0);
                mmabf(acc[nj*2],   ah, bl0);
                mmabf(acc[nj*2],   al, bh0);
                mmabf(acc[nj*2+1], ah, bh1);
                mmabf(acc[nj*2+1], ah, bl1);
                mmabf(acc[nj*2+1], al, bh1);
            }
        }
        __syncthreads();
    }
    #undef CTX_LOADS

    float* Cb = g_cpart + (size_t)qc*PROJ_ELEMS + (size_t)bh*SEQ*HD;
    #pragma unroll
    for (int ni=0;ni<4;ni++){
        int drow = wm*16 + gr;
        int col  = nb + wn*32 + ni*8 + tc*2;
        Cb[(size_t)col*HD + drow]         = acc[ni][0];
        Cb[(size_t)(col+1)*HD + drow]     = acc[ni][1];
        Cb[(size_t)col*HD + drow+8]       = acc[ni][2];
        Cb[(size_t)(col+1)*HD + drow+8]   = acc[ni][3];
    }
}

// ---------------------------------------------------------------------------
// Kernel 5: output = (sum of 4 ctx partials) @ wp^T + bp   (3-term bf16)
// ---------------------------------------------------------------------------
__global__ __launch_bounds__(256) void outproj_kernel(const float* __restrict__ W,
        const float* __restrict__ bias, float* __restrict__ out){
    __shared__ __align__(16) uint32_t Chi[128*STR], Clo[128*STR];
    __shared__ __align__(16) uint32_t Whi[64*STR],  Wlo[64*STR];
    int tid = threadIdx.x;
    int m0 = blockIdx.x*128;
    int b = m0>>10, l0 = m0&1023;
    int w = tid>>5, wm = w>>1, wn = w&1;
    int lane = tid&31, gr = lane>>2, c2 = (lane&3)*2;

    float acc[2][4][4] = {};
    for (int k0=0; k0<QDIM; k0+=32){
        int h = k0>>6, off = k0&63;
        const float* Cg = g_cpart + ((size_t)(b*NH+h)*SEQ + l0)*HD + off;
        __syncthreads();
        #pragma unroll
        for (int i=0;i<4;i++){
            int lin = tid + i*256;
            int r = lin>>3, c4 = lin&7;
            size_t o = (size_t)r*HD + c4*4;
            float4 a0 = *(const float4*)(Cg + o);
            float4 a1 = *(const float4*)(Cg + (size_t)PROJ_ELEMS + o);
            float4 a2 = *(const float4*)(Cg + (size_t)2*PROJ_ELEMS + o);
            float4 a3 = *(const float4*)(Cg + (size_t)3*PROJ_ELEMS + o);
            float4 s;
            s.x = (a0.x+a1.x)+(a2.x+a3.x);
            s.y = (a0.y+a1.y)+(a2.y+a3.y);
            s.z = (a0.z+a1.z)+(a2.z+a3.z);
            s.w = (a0.w+a1.w)+(a2.w+a3.w);
            uint32_t h0,l0_,h1,l1;
            packsplit(s.x, s.y, h0, l0_);
            packsplit(s.z, s.w, h1, l1);
            Chi[r*STR + c4*2] = h0; Chi[r*STR + c4*2+1] = h1;
            Clo[r*STR + c4*2] = l0_; Clo[r*STR + c4*2+1] = l1;
        }
        #pragma unroll
        for (int i=0;i<2;i++){
            int lin = tid + i*256;
            int r = lin>>3, c4 = lin&7;
            float4 wv = *(const float4*)(W + (size_t)r*QDIM + k0 + c4*4);
            uint32_t h0,l0_,h1,l1;
            packsplit(wv.x, wv.y, h0, l0_);
            packsplit(wv.z, wv.w, h1, l1);
            Whi[r*STR + c4*2] = h0; Whi[r*STR + c4*2+1] = h1;
            Wlo[r*STR + c4*2] = l0_; Wlo[r*STR + c4*2+1] = l1;
        }
        __syncthreads();
        #pragma unroll
        for (int ks=0; ks<2; ks++){
            int kp = ks*8;
            uint32_t ah[2][4], al[2][4];
            #pragma unroll
            for (int mi=0;mi<2;mi++){
                ldsmA(Chi, wm*32+mi*16, kp, ah[mi]);
                ldsmA(Clo, wm*32+mi*16, kp, al[mi]);
            }
            #pragma unroll
            for (int nj=0;nj<2;nj++){
                uint32_t bh0[2], bh1[2], bl0[2], bl1[2];
                ldsmB2(Whi, wn*32+nj*16, kp, bh0, bh1);
                ldsmB2(Wlo, wn*32+nj*16, kp, bl0, bl1);
                #pragma unroll
                for (int mi=0;mi<2;mi++){
                    mmabf(acc[mi][nj*2],   ah[mi], bh0);
                    mmabf(acc[mi][nj*2],   ah[mi], bl0);
                    mmabf(acc[mi][nj*2],   al[mi], bh0);
                    mmabf(acc[mi][nj*2+1], ah[mi], bh1);
                    mmabf(acc[mi][nj*2+1], ah[mi], bl1);
                    mmabf(acc[mi][nj*2+1], al[mi], bh1);
                }
            }
        }
    }
    #pragma unroll
    for (int mi=0;mi<2;mi++)
    #pragma unroll
    for (int ni=0;ni<4;ni++){
        int row = m0 + wm*32 + mi*16 + gr;
        int col = wn*32 + ni*8 + c2;
        float2 bb = *(const float2*)(bias + col);
        float2 v0 = {acc[mi][ni][0]+bb.x, acc[mi][ni][1]+bb.y};
        float2 v1 = {acc[mi][ni][2]+bb.x, acc[mi][ni][3]+bb.y};
        *(float2*)(out + (size_t)row*HD + col) = v0;
        *(float2*)(out + (size_t)(row+8)*HD + col) = v1;
    }
}

// ---------------------------------------------------------------------------
extern "C" void kernel_launch(void* const* d_in, const int* in_sizes, int n_in,
                              void* d_out, int out_size) {
    const float* q  = (const float*)d_in[0];
    const float* k  = (const float*)d_in[1];
    const float* v  = (const float*)d_in[2];
    const float* wq = (const float*)d_in[3];
    const float* bq = (const float*)d_in[4];
    const float* wk = (const float*)d_in[5];
    const float* bk = (const float*)d_in[6];
    const float* wv = (const float*)d_in[7];
    const float* bv = (const float*)d_in[8];
    const float* wp = (const float*)d_in[9];
    const float* bp = (const float*)d_in[10];

    float* out  = (float*)d_out;
    float* attn = out + OUT_ELEMS;

    dim3 projGrid(NH, (BATCH*SEQ)/128, 3);            // (8, 32, 3)
    proj_all_kernel<<<projGrid, 256>>>(q, k, v, wq, wk, wv, bq, bk, bv);

    dim3 scoreGrid(SEQ/128, SEQ/128, BH);             // (8, 8, 32)
    scores_exp_kernel<<<scoreGrid, 512>>>(attn);

    rowsum_kernel<<<NROWS/256, 256>>>();

    dim3 ctxGrid(SEQ/64, BH, QCHUNKS);                // (16, 32, 4)
    context_norm_kernel<<<ctxGrid, 256>>>(attn);

    outproj_kernel<<<(BATCH*SEQ)/128, 256>>>(wp, bp, out);
}

// round 11
// speedup vs baseline: 1.3110x; 1.0904x over previous
#include <cuda_runtime.h>
#include <cuda_bf16.h>
#include <math.h>
#include <stdint.h>

#define BATCH 4
#define SEQ   1024
#define QDIM  512
#define NH    8
#define HD    64
#define BH    (BATCH*NH)
#define OUT_ELEMS  (BATCH*SEQ*HD)
#define PROJ_ELEMS (BATCH*NH*SEQ*HD)
#define NROWS (BH*SEQ)
#define QCHUNKS 4
#define STR 20    // k-pair-major smem row stride (words)
#define TSTR 36   // natural-orientation smem row stride (words)

__device__ float g_q[PROJ_ELEMS];
__device__ float g_k[PROJ_ELEMS];
__device__ float g_v[PROJ_ELEMS];
__device__ float g_cpart[QCHUNKS*PROJ_ELEMS];
__device__ float g_partial[NROWS * 8];
__device__ float g_rinv[NROWS];

// ---------------------------------------------------------------------------
// bf16 split helpers
// ---------------------------------------------------------------------------
__device__ __forceinline__ uint32_t packbf(float x, float y){
    __nv_bfloat162 t = __floats2bfloat162_rn(x, y);
    return *(uint32_t*)&t;
}
__device__ __forceinline__ void packsplit(float x, float y, uint32_t& hi, uint32_t& lo){
    __nv_bfloat16 xh = __float2bfloat16_rn(x);
    __nv_bfloat16 yh = __float2bfloat16_rn(y);
    __nv_bfloat162 h; h.x = xh; h.y = yh;
    hi = *(uint32_t*)&h;
    lo = packbf(x - __bfloat162float(xh), y - __bfloat162float(yh));
}
__device__ __forceinline__ void mmabf(float c[4], const uint32_t a[4], const uint32_t b[2]){
    asm volatile("mma.sync.aligned.m16n8k16.row.col.f32.bf16.bf16.f32 "
        "{%0,%1,%2,%3},{%4,%5,%6,%7},{%8,%9},{%0,%1,%2,%3};"
        : "+f"(c[0]),"+f"(c[1]),"+f"(c[2]),"+f"(c[3])
        : "r"(a[0]),"r"(a[1]),"r"(a[2]),"r"(a[3]),"r"(b[0]),"r"(b[1]));
}

__device__ __forceinline__ uint32_t smem_u32(const void* p){
    uint32_t a;
    asm("{.reg .u64 t; cvta.to.shared.u64 t, %1; cvt.u32.u64 %0, t;}" : "=r"(a) : "l"(p));
    return a;
}
// ---- k-pair-major (non-trans) loaders, stride STR ----
__device__ __forceinline__ void ldsmA(const uint32_t* S, int row0, int kp, uint32_t a[4]){
    int lane = threadIdx.x & 31;
    const uint32_t* p = S + (row0 + (lane & 15))*STR + kp + ((lane >> 4) << 2);
    uint32_t addr = smem_u32(p);
    asm volatile("ldmatrix.sync.aligned.m8n8.x4.shared.b16 {%0,%1,%2,%3}, [%4];"
        : "=r"(a[0]),"=r"(a[1]),"=r"(a[2]),"=r"(a[3]) : "r"(addr));
}
__device__ __forceinline__ void ldsmB2(const uint32_t* S, int n0, int kp,
                                       uint32_t b0[2], uint32_t b1[2]){
    int lane = threadIdx.x & 31;
    int row = n0 + ((lane >> 4) << 3) + (lane & 7);
    int ko  = kp + (((lane >> 3) & 1) << 2);
    uint32_t addr = smem_u32(S + row*STR + ko);
    asm volatile("ldmatrix.sync.aligned.m8n8.x4.shared.b16 {%0,%1,%2,%3}, [%4];"
        : "=r"(b0[0]),"=r"(b0[1]),"=r"(b1[0]),"=r"(b1[1]) : "r"(addr));
}
// ---- natural-orientation (trans) loaders, stride TSTR; memory rows = k ----
__device__ __forceinline__ void ldsmAT(const uint32_t* S, int k0, int m0, uint32_t a[4]){
    int lane = threadIdx.x & 31;
    int row  = k0 + (lane & 7) + ((lane & 16) >> 1);
    int woff = (m0 >> 1) + ((lane & 8) >> 1);
    uint32_t addr = smem_u32(S + row*TSTR + woff);
    asm volatile("ldmatrix.sync.aligned.m8n8.x4.trans.shared.b16 {%0,%1,%2,%3}, [%4];"
        : "=r"(a[0]),"=r"(a[1]),"=r"(a[2]),"=r"(a[3]) : "r"(addr));
}
__device__ __forceinline__ void ldsmBT2(const uint32_t* S, int k0, int n0,
                                        uint32_t b0[2], uint32_t b1[2]){
    int lane = threadIdx.x & 31;
    int row  = k0 + (lane & 7) + (lane & 8);
    int woff = (n0 >> 1) + ((lane & 16) >> 2);
    uint32_t addr = smem_u32(S + row*TSTR + woff);
    asm volatile("ldmatrix.sync.aligned.m8n8.x4.trans.shared.b16 {%0,%1,%2,%3}, [%4];"
        : "=r"(b0[0]),"=r"(b0[1]),"=r"(b1[0]),"=r"(b1[1]) : "r"(addr));
}

// ---------------------------------------------------------------------------
// Kernel 1: all three projections  Y = X @ W^T + b  (3-term bf16) -> [b,h,l,d]
// ---------------------------------------------------------------------------
__global__ __launch_bounds__(256) void proj_all_kernel(
        const float* __restrict__ x0, const float* __restrict__ x1, const float* __restrict__ x2,
        const float* __restrict__ w0, const float* __restrict__ w1, const float* __restrict__ w2,
        const float* __restrict__ b0, const float* __restrict__ b1, const float* __restrict__ b2){
    __shared__ __align__(16) uint32_t Xhi[128*STR], Xlo[128*STR];
    __shared__ __align__(16) uint32_t Whi[64*STR],  Wlo[64*STR];
    int sel = blockIdx.z;
    const float* X = sel==0 ? x0 : sel==1 ? x1 : x2;
    const float* W = sel==0 ? w0 : sel==1 ? w1 : w2;
    const float* bias = sel==0 ? b0 : sel==1 ? b1 : b2;
    float* dst = sel==0 ? g_q : sel==1 ? g_k : g_v;

    int tid = threadIdx.x;
    int h = blockIdx.x, n0 = h*64;
    int m0 = blockIdx.y*128;
    int w = tid>>5, wm = w>>1, wn = w&1;
    int lane = tid&31, gr = lane>>2, c2 = (lane&3)*2;

    float acc[2][4][4] = {};
    for (int k0=0; k0<QDIM; k0+=32){
        __syncthreads();
        #pragma unroll
        for (int i=0;i<4;i++){
            int lin = tid + i*256;
            int r = lin>>3, c4 = lin&7;
            float4 xv = *(const float4*)(X + (size_t)(m0+r)*QDIM + k0 + c4*4);
            uint32_t h0,l0,h1,l1;
            packsplit(xv.x, xv.y, h0, l0);
            packsplit(xv.z, xv.w, h1, l1);
            Xhi[r*STR + c4*2]   = h0; Xhi[r*STR + c4*2+1] = h1;
            Xlo[r*STR + c4*2]   = l0; Xlo[r*STR + c4*2+1] = l1;
        }
        #pragma unroll
        for (int i=0;i<2;i++){
            int lin = tid + i*256;
            int r = lin>>3, c4 = lin&7;
            float4 wv = *(const float4*)(W + (size_t)(n0+r)*QDIM + k0 + c4*4);
            uint32_t h0,l0,h1,l1;
            packsplit(wv.x, wv.y, h0, l0);
            packsplit(wv.z, wv.w, h1, l1);
            Whi[r*STR + c4*2]   = h0; Whi[r*STR + c4*2+1] = h1;
            Wlo[r*STR + c4*2]   = l0; Wlo[r*STR + c4*2+1] = l1;
        }
        __syncthreads();
        #pragma unroll
        for (int ks=0; ks<2; ks++){
            int kp = ks*8;
            uint32_t ah[2][4], al[2][4];
            #pragma unroll
            for (int mi=0;mi<2;mi++){
                ldsmA(Xhi, wm*32+mi*16, kp, ah[mi]);
                ldsmA(Xlo, wm*32+mi*16, kp, al[mi]);
            }
            #pragma unroll
            for (int nj=0;nj<2;nj++){
                uint32_t bh0[2], bh1[2], bl0[2], bl1[2];
                ldsmB2(Whi, wn*32+nj*16, kp, bh0, bh1);
                ldsmB2(Wlo, wn*32+nj*16, kp, bl0, bl1);
                #pragma unroll
                for (int mi=0;mi<2;mi++){
                    mmabf(acc[mi][nj*2],   ah[mi], bh0);
                    mmabf(acc[mi][nj*2],   ah[mi], bl0);
                    mmabf(acc[mi][nj*2],   al[mi], bh0);
                    mmabf(acc[mi][nj*2+1], ah[mi], bh1);
                    mmabf(acc[mi][nj*2+1], ah[mi], bl1);
                    mmabf(acc[mi][nj*2+1], al[mi], bh1);
                }
            }
        }
    }
    int b = m0>>10, l0 = m0&1023;
    float* base = dst + (size_t)(b*NH+h)*SEQ*HD;
    #pragma unroll
    for (int mi=0;mi<2;mi++)
    #pragma unroll
    for (int ni=0;ni<4;ni++){
        int row = l0 + wm*32 + mi*16 + gr;
        int col = wn*32 + ni*8 + c2;
        float2 bb = *(const float2*)(bias + n0 + col);
        float2 v0 = {acc[mi][ni][0]+bb.x, acc[mi][ni][1]+bb.y};
        float2 v1 = {acc[mi][ni][2]+bb.x, acc[mi][ni][3]+bb.y};
        *(float2*)(base + (size_t)row*HD + col) = v0;
        *(float2*)(base + (size_t)(row+8)*HD + col) = v1;
    }
}

// ---------------------------------------------------------------------------
// Kernel 2: P = exp(0.5 * Q K^T) (3-term bf16) -> attn (unnormalized) + partials
// grid (8 kb, 8 qb, 32 bh), 512 threads, tile 128q x 128k, warp 32x32
// P stores use .cs (read exactly once later; keep out of L2 working set)
// ---------------------------------------------------------------------------
__global__ __launch_bounds__(512) void scores_exp_kernel(float* __restrict__ attn){
    __shared__ __align__(16) uint32_t Qhi[128*STR], Qlo[128*STR];
    __shared__ __align__(16) uint32_t Khi[128*STR], Klo[128*STR];
    __shared__ float sums[128][4];

    int tid = threadIdx.x;
    int kb = blockIdx.x, q0b = blockIdx.y*128, bh = blockIdx.z;
    int w = tid>>5, wq = w>>2, wk = w&3;
    int lane = tid&31, gr = lane>>2, c2 = (lane&3)*2;
    const float* Qg = g_q + (size_t)(bh*SEQ + q0b)*HD;
    const float* Kg = g_k + (size_t)(bh*SEQ + kb*128)*HD;

    float acc[2][4][4] = {};
    #pragma unroll
    for (int dt=0; dt<2; dt++){
        int d0 = dt*32;
        __syncthreads();
        #pragma unroll
        for (int i=0;i<2;i++){
            int lin = tid + i*512;
            int r = lin>>3, c4 = lin&7;
            float4 xq = *(const float4*)(Qg + (size_t)r*HD + d0 + c4*4);
            float4 xk = *(const float4*)(Kg + (size_t)r*HD + d0 + c4*4);
            uint32_t h0,l0,h1,l1;
            packsplit(xq.x, xq.y, h0, l0); packsplit(xq.z, xq.w, h1, l1);
            Qhi[r*STR + c4*2] = h0; Qhi[r*STR + c4*2+1] = h1;
            Qlo[r*STR + c4*2] = l0; Qlo[r*STR + c4*2+1] = l1;
            packsplit(xk.x, xk.y, h0, l0); packsplit(xk.z, xk.w, h1, l1);
            Khi[r*STR + c4*2] = h0; Khi[r*STR + c4*2+1] = h1;
            Klo[r*STR + c4*2] = l0; Klo[r*STR + c4*2+1] = l1;
        }
        __syncthreads();
        #pragma unroll
        for (int ks=0; ks<2; ks++){
            int kp = ks*8;
            uint32_t ah[2][4], al[2][4];
            #pragma unroll
            for (int mi=0;mi<2;mi++){
                ldsmA(Qhi, wq*32+mi*16, kp, ah[mi]);
                ldsmA(Qlo, wq*32+mi*16, kp, al[mi]);
            }
            #pragma unroll
            for (int nj=0;nj<2;nj++){
                uint32_t bh0[2], bh1[2], bl0[2], bl1[2];
                ldsmB2(Khi, wk*32+nj*16, kp, bh0, bh1);
                ldsmB2(Klo, wk*32+nj*16, kp, bl0, bl1);
                #pragma unroll
                for (int mi=0;mi<2;mi++){
                    mmabf(acc[mi][nj*2],   ah[mi], bh0);
                    mmabf(acc[mi][nj*2],   ah[mi], bl0);
                    mmabf(acc[mi][nj*2],   al[mi], bh0);
                    mmabf(acc[mi][nj*2+1], ah[mi], bh1);
                    mmabf(acc[mi][nj*2+1], ah[mi], bl1);
                    mmabf(acc[mi][nj*2+1], al[mi], bh1);
                }
            }
        }
    }

    float* Ab = attn + (size_t)bh*SEQ*SEQ;
    float rs[2][2] = {};
    #pragma unroll
    for (int mi=0;mi<2;mi++)
    #pragma unroll
    for (int ni=0;ni<4;ni++){
        float e0 = __expf(acc[mi][ni][0]*0.5f);
        float e1 = __expf(acc[mi][ni][1]*0.5f);
        float e2 = __expf(acc[mi][ni][2]*0.5f);
        float e3 = __expf(acc[mi][ni][3]*0.5f);
        int row = q0b + wq*32 + mi*16 + gr;
        int col = kb*128 + wk*32 + ni*8 + c2;
        float2 v0 = {e0, e1}, v1 = {e2, e3};
        __stcs((float2*)(Ab + (size_t)row*SEQ + col), v0);
        __stcs((float2*)(Ab + (size_t)(row+8)*SEQ + col), v1);
        rs[mi][0] += e0 + e1;
        rs[mi][1] += e2 + e3;
    }
    #pragma unroll
    for (int mi=0;mi<2;mi++)
    #pragma unroll
    for (int j=0;j<2;j++){
        float s = rs[mi][j];
        s += __shfl_xor_sync(0xffffffffu, s, 1);
        s += __shfl_xor_sync(0xffffffffu, s, 2);
        rs[mi][j] = s;
    }
    if ((lane&3)==0){
        #pragma unroll
        for (int mi=0;mi<2;mi++)
        #pragma unroll
        for (int j=0;j<2;j++)
            sums[wq*32 + mi*16 + gr + j*8][wk] = rs[mi][j];
    }
    __syncthreads();
    if (tid < 128){
        float t = sums[tid][0] + sums[tid][1] + sums[tid][2] + sums[tid][3];
        g_partial[(((size_t)bh*SEQ + q0b + tid)<<3) + kb] = t;
    }
}

// ---------------------------------------------------------------------------
// Kernel 3: row-sum reduce -> 1/S
// ---------------------------------------------------------------------------
__global__ __launch_bounds__(256) void rowsum_kernel(){
    int r = blockIdx.x*256 + threadIdx.x;
    const float* p = g_partial + ((size_t)r<<3);
    float s = ((p[0]+p[1])+(p[2]+p[3])) + ((p[4]+p[5])+(p[6]+p[7]));
    g_rinv[r] = 1.0f / s;
}

// ---------------------------------------------------------------------------
// Kernel 4: normalize attn in place + PARTIAL context (3-term bf16)
// grid (16 n-tiles of 64, 32 bh, 4 q-chunks), 256 threads.
// Double-buffered smem (ONE sync per 32-q step) + register prefetch.
// attn loads/stores use .cs streaming hints (touched exactly once here).
// ---------------------------------------------------------------------------
__global__ __launch_bounds__(256) void context_norm_kernel(float* __restrict__ attn){
    __shared__ __align__(16) uint32_t Vhi[2][32*TSTR], Vlo[2][32*TSTR];
    __shared__ __align__(16) uint32_t Ahi[2][32*TSTR], Alo[2][32*TSTR];
    int tid = threadIdx.x;
    int nb = blockIdx.x*64, bh = blockIdx.y, qc = blockIdx.z;
    int w = tid>>5, wm = w>>1, wn = w&1;   // wm: 4 x m16 (d), wn: 2 x n32
    int lane = tid&31, gr = lane>>2, tc = lane&3;
    float* Ag = attn + (size_t)bh*SEQ*SEQ + nb;
    const float* Vg = g_v + (size_t)bh*SEQ*HD;
    const float* rinv = g_rinv + (size_t)bh*SEQ;

    float4 vr[2], ar[2]; float ri[2];
    #define CTX_LOADS(Q0)                                                       \
        _Pragma("unroll")                                                       \
        for (int i=0;i<2;i++){                                                  \
            int idx = tid + i*256; int r = idx>>4, c4 = idx&15;                 \
            vr[i] = *(const float4*)(Vg + (size_t)((Q0)+r)*HD + c4*4);          \
            ar[i] = __ldcs((const float4*)(Ag + (size_t)((Q0)+r)*SEQ + c4*4));  \
            ri[i] = rinv[(Q0)+r];                                               \
        }

    float acc[4][4] = {};
    int qlo = qc*(SEQ/QCHUNKS), qhi_ = qlo + SEQ/QCHUNKS;
    CTX_LOADS(qlo);
    int s = 0;
    for (int q0=qlo; q0<qhi_; q0+=32, s^=1){
        #pragma unroll
        for (int i=0;i<2;i++){
            int idx = tid + i*256; int r = idx>>4, c4 = idx&15;
            uint32_t h0,l0,h1,l1;
            packsplit(vr[i].x, vr[i].y, h0, l0);
            packsplit(vr[i].z, vr[i].w, h1, l1);
            *(uint2*)&Vhi[s][r*TSTR + c4*2] = make_uint2(h0, h1);
            *(uint2*)&Vlo[s][r*TSTR + c4*2] = make_uint2(l0, l1);
            float4 a = ar[i]; float rv = ri[i];
            a.x*=rv; a.y*=rv; a.z*=rv; a.w*=rv;
            __stcs((float4*)(Ag + (size_t)(q0+r)*SEQ + c4*4), a);
            packsplit(a.x, a.y, h0, l0);
            packsplit(a.z, a.w, h1, l1);
            *(uint2*)&Ahi[s][r*TSTR + c4*2] = make_uint2(h0, h1);
            *(uint2*)&Alo[s][r*TSTR + c4*2] = make_uint2(l0, l1);
        }
        __syncthreads();
        if (q0+32 < qhi_){ CTX_LOADS(q0+32); }
        #pragma unroll
        for (int ks=0; ks<2; ks++){
            int k0 = ks*16;
            uint32_t ah[4], al[4];
            ldsmAT(Vhi[s], k0, wm*16, ah);
            ldsmAT(Vlo[s], k0, wm*16, al);
            #pragma unroll
            for (int nj=0;nj<2;nj++){
                uint32_t bh0[2], bh1[2], bl0[2], bl1[2];
                ldsmBT2(Ahi[s], k0, wn*32+nj*16, bh0, bh1);
                ldsmBT2(Alo[s], k0, wn*32+nj*16, bl0, bl1);
                mmabf(acc[nj*2],   ah, bh0);
                mmabf(acc[nj*2],   ah, bl0);
                mmabf(acc[nj*2],   al, bh0);
                mmabf(acc[nj*2+1], ah, bh1);
                mmabf(acc[nj*2+1], ah, bl1);
                mmabf(acc[nj*2+1], al, bh1);
            }
        }
        // no trailing sync: next iter writes the OTHER buffer; its previous
        // readers (MMA of iter-1) are already fenced by this iter's sync.
    }
    #undef CTX_LOADS

    float* Cb = g_cpart + (size_t)qc*PROJ_ELEMS + (size_t)bh*SEQ*HD;
    #pragma unroll
    for (int ni=0;ni<4;ni++){
        int drow = wm*16 + gr;
        int col  = nb + wn*32 + ni*8 + tc*2;
        Cb[(size_t)col*HD + drow]         = acc[ni][0];
        Cb[(size_t)(col+1)*HD + drow]     = acc[ni][1];
        Cb[(size_t)col*HD + drow+8]       = acc[ni][2];
        Cb[(size_t)(col+1)*HD + drow+8]   = acc[ni][3];
    }
}

// ---------------------------------------------------------------------------
// Kernel 5: output = (sum of 4 ctx partials) @ wp^T + bp   (3-term bf16)
// ---------------------------------------------------------------------------
__global__ __launch_bounds__(256) void outproj_kernel(const float* __restrict__ W,
        const float* __restrict__ bias, float* __restrict__ out){
    __shared__ __align__(16) uint32_t Chi[128*STR], Clo[128*STR];
    __shared__ __align__(16) uint32_t Whi[64*STR],  Wlo[64*STR];
    int tid = threadIdx.x;
    int m0 = blockIdx.x*128;
    int b = m0>>10, l0 = m0&1023;
    int w = tid>>5, wm = w>>1, wn = w&1;
    int lane = tid&31, gr = lane>>2, c2 = (lane&3)*2;

    float acc[2][4][4] = {};
    for (int k0=0; k0<QDIM; k0+=32){
        int h = k0>>6, off = k0&63;
        const float* Cg = g_cpart + ((size_t)(b*NH+h)*SEQ + l0)*HD + off;
        __syncthreads();
        #pragma unroll
        for (int i=0;i<4;i++){
            int lin = tid + i*256;
            int r = lin>>3, c4 = lin&7;
            size_t o = (size_t)r*HD + c4*4;
            float4 a0 = *(const float4*)(Cg + o);
            float4 a1 = *(const float4*)(Cg + (size_t)PROJ_ELEMS + o);
            float4 a2 = *(const float4*)(Cg + (size_t)2*PROJ_ELEMS + o);
            float4 a3 = *(const float4*)(Cg + (size_t)3*PROJ_ELEMS + o);
            float4 s;
            s.x = (a0.x+a1.x)+(a2.x+a3.x);
            s.y = (a0.y+a1.y)+(a2.y+a3.y);
            s.z = (a0.z+a1.z)+(a2.z+a3.z);
            s.w = (a0.w+a1.w)+(a2.w+a3.w);
            uint32_t h0,l0_,h1,l1;
            packsplit(s.x, s.y, h0, l0_);
            packsplit(s.z, s.w, h1, l1);
            Chi[r*STR + c4*2] = h0; Chi[r*STR + c4*2+1] = h1;
            Clo[r*STR + c4*2] = l0_; Clo[r*STR + c4*2+1] = l1;
        }
        #pragma unroll
        for (int i=0;i<2;i++){
            int lin = tid + i*256;
            int r = lin>>3, c4 = lin&7;
            float4 wv = *(const float4*)(W + (size_t)r*QDIM + k0 + c4*4);
            uint32_t h0,l0_,h1,l1;
            packsplit(wv.x, wv.y, h0, l0_);
            packsplit(wv.z, wv.w, h1, l1);
            Whi[r*STR + c4*2] = h0; Whi[r*STR + c4*2+1] = h1;
            Wlo[r*STR + c4*2] = l0_; Wlo[r*STR + c4*2+1] = l1;
        }
        __syncthreads();
        #pragma unroll
        for (int ks=0; ks<2; ks++){
            int kp = ks*8;
            uint32_t ah[2][4], al[2][4];
            #pragma unroll
            for (int mi=0;mi<2;mi++){
                ldsmA(Chi, wm*32+mi*16, kp, ah[mi]);
                ldsmA(Clo, wm*32+mi*16, kp, al[mi]);
            }
            #pragma unroll
            for (int nj=0;nj<2;nj++){
                uint32_t bh0[2], bh1[2], bl0[2], bl1[2];
                ldsmB2(Whi, wn*32+nj*16, kp, bh0, bh1);
                ldsmB2(Wlo, wn*32+nj*16, kp, bl0, bl1);
                #pragma unroll
                for (int mi=0;mi<2;mi++){
                    mmabf(acc[mi][nj*2],   ah[mi], bh0);
                    mmabf(acc[mi][nj*2],   ah[mi], bl0);
                    mmabf(acc[mi][nj*2],   al[mi], bh0);
                    mmabf(acc[mi][nj*2+1], ah[mi], bh1);
                    mmabf(acc[mi][nj*2+1], ah[mi], bl1);
                    mmabf(acc[mi][nj*2+1], al[mi], bh1);
                }
            }
        }
    }
    #pragma unroll
    for (int mi=0;mi<2;mi++)
    #pragma unroll
    for (int ni=0;ni<4;ni++){
        int row = m0 + wm*32 + mi*16 + gr;
        int col = wn*32 + ni*8 + c2;
        float2 bb = *(const float2*)(bias + col);
        float2 v0 = {acc[mi][ni][0]+bb.x, acc[mi][ni][1]+bb.y};
        float2 v1 = {acc[mi][ni][2]+bb.x, acc[mi][ni][3]+bb.y};
        *(float2*)(out + (size_t)row*HD + col) = v0;
        *(float2*)(out + (size_t)(row+8)*HD + col) = v1;
    }
}

// ---------------------------------------------------------------------------
extern "C" void kernel_launch(void* const* d_in, const int* in_sizes, int n_in,
                              void* d_out, int out_size) {
    const float* q  = (const float*)d_in[0];
    const float* k  = (const float*)d_in[1];
    const float* v  = (const float*)d_in[2];
    const float* wq = (const float*)d_in[3];
    const float* bq = (const float*)d_in[4];
    const float* wk = (const float*)d_in[5];
    const float* bk = (const float*)d_in[6];
    const float* wv = (const float*)d_in[7];
    const float* bv = (const float*)d_in[8];
    const float* wp = (const float*)d_in[9];
    const float* bp = (const float*)d_in[10];

    float* out  = (float*)d_out;
    float* attn = out + OUT_ELEMS;

    dim3 projGrid(NH, (BATCH*SEQ)/128, 3);            // (8, 32, 3)
    proj_all_kernel<<<projGrid, 256>>>(q, k, v, wq, wk, wv, bq, bk, bv);

    dim3 scoreGrid(SEQ/128, SEQ/128, BH);             // (8, 8, 32)
    scores_exp_kernel<<<scoreGrid, 512>>>(attn);

    rowsum_kernel<<<NROWS/256, 256>>>();

    dim3 ctxGrid(SEQ/64, BH, QCHUNKS);                // (16, 32, 4)
    context_norm_kernel<<<ctxGrid, 256>>>(attn);

    outproj_kernel<<<(BATCH*SEQ)/128, 256>>>(wp, bp, out);
}